// round 3
// baseline (speedup 1.0000x reference)
#include <cuda_runtime.h>
#include <math.h>

// ---------------- problem constants ----------------
#define NN  100000
#define HD  128
#define EE  1600000
#define FIN 256
#define KD  5

// ---------------- scratch (static __device__, no allocation) ----------------
__device__ float g_h   [(size_t)NN * HD];
__device__ float g_h2  [(size_t)NN * HD];
__device__ float g_agg [(size_t)NN * HD];
__device__ float g_feat[(size_t)NN * HD];
__device__ float g_y0  [(size_t)NN * HD];
__device__ float g_y1  [(size_t)NN * HD];

__device__ int g_src[EE];
__device__ int g_dstv[EE];
__device__ int g_csr_src[EE];
__device__ int g_counts[NN];
__device__ int g_incl[NN];
__device__ int g_offs[NN + 1];
__device__ int g_cursor[NN];
__device__ int g_bsum[256];
__device__ int g_flag64;

// ---------------- edge-index dtype detection ----------------
// If the buffer is int64 (little-endian, values < 2^31), every odd 32-bit word
// of the first 32 elements is zero. For int32 data those words are random edge
// indices; P(all 32 are zero) ~ (1e-5)^32 ~ 0.
__global__ void detect_layout_kernel(const unsigned* __restrict__ p) {
    unsigned any = 0;
#pragma unroll
    for (int i = 1; i < 64; i += 2) any |= p[i];
    g_flag64 = (any == 0) ? 1 : 0;
}

__global__ void extract_edges_kernel(const void* __restrict__ edge_index, int E) {
    int i = blockIdx.x * blockDim.x + threadIdx.x;
    if (i >= E) return;
    if (g_flag64) {
        const long long* p = (const long long*)edge_index;
        g_src[i]  = (int)p[i];
        g_dstv[i] = (int)p[(size_t)E + i];
    } else {
        const int* p = (const int*)edge_index;
        g_src[i]  = p[i];
        g_dstv[i] = p[E + i];
    }
}

// ---------------- CSR build (counting sort by dst) ----------------
__global__ void zero_counts_kernel(int n) {
    int i = blockIdx.x * blockDim.x + threadIdx.x;
    if (i < n) g_counts[i] = 0;
}

__global__ void histogram_kernel(int E) {
    int i = blockIdx.x * blockDim.x + threadIdx.x;
    if (i < E) atomicAdd(&g_counts[g_dstv[i]], 1);
}

// blockwise inclusive scan (1024 elems / block)
__global__ void scan1_kernel(int n) {
    __shared__ int s[1024];
    int i = blockIdx.x * 1024 + threadIdx.x;
    int v = (i < n) ? g_counts[i] : 0;
    s[threadIdx.x] = v;
    __syncthreads();
#pragma unroll
    for (int off = 1; off < 1024; off <<= 1) {
        int t = (threadIdx.x >= off) ? s[threadIdx.x - off] : 0;
        __syncthreads();
        s[threadIdx.x] += t;
        __syncthreads();
    }
    if (i < n) g_incl[i] = s[threadIdx.x];
    if (threadIdx.x == 1023) g_bsum[blockIdx.x] = s[1023];
}

__global__ void scan2_kernel(int nb) {
    if (threadIdx.x == 0 && blockIdx.x == 0) {
        int run = 0;
        for (int i = 0; i < nb; ++i) {
            int v = g_bsum[i];
            g_bsum[i] = run;
            run += v;
        }
    }
}

__global__ void scan3_kernel(int n, int E) {
    int i = blockIdx.x * blockDim.x + threadIdx.x;
    if (i >= n) return;
    int off = g_bsum[i >> 10] + g_incl[i] - g_counts[i];
    g_offs[i] = off;
    g_cursor[i] = off;
    if (i == n - 1) g_offs[n] = E;
}

__global__ void scatter_csr_kernel(int E) {
    int i = blockIdx.x * blockDim.x + threadIdx.x;
    if (i >= E) return;
    int d = g_dstv[i];
    int p = atomicAdd(&g_cursor[d], 1);
    g_csr_src[p] = g_src[i];
}

// ---------------- mean aggregation: one warp per node ----------------
__global__ void mean_agg_kernel(const float* __restrict__ h, float* __restrict__ agg, int n) {
    int warp = (blockIdx.x * blockDim.x + threadIdx.x) >> 5;
    int lane = threadIdx.x & 31;
    if (warp >= n) return;
    int s = g_offs[warp];
    int e = g_offs[warp + 1];
    float4 acc = make_float4(0.f, 0.f, 0.f, 0.f);
    for (int i = s; i < e; ++i) {
        int src = g_csr_src[i];
        float4 v = ((const float4*)(h + (size_t)src * HD))[lane];
        acc.x += v.x; acc.y += v.y; acc.z += v.z; acc.w += v.w;
    }
    float inv = 1.0f / (float)max(e - s, 1);
    acc.x *= inv; acc.y *= inv; acc.z *= inv; acc.w *= inv;
    ((float4*)(agg + (size_t)warp * HD))[lane] = acc;
}

// ---------------- tiled SGEMM: C[M,128] = act(A1@W1 + A2@W2 + b) ----------------
// A row-major [M,K], W row-major [K,128]. Two-source support for conv layers.
#define BM 128
#define BN 128
#define BK 32

__global__ void __launch_bounds__(256) gemm_kernel(
    const float* __restrict__ A1, const float* __restrict__ W1, int K1,
    const float* __restrict__ A2, const float* __restrict__ W2, int K2,
    const float* __restrict__ bias, float* __restrict__ C, int M, int do_relu)
{
    __shared__ float As[BK][BM + 4];
    __shared__ float Wt[BK][BN];

    int tid = threadIdx.x;
    int tx = tid & 15;       // col group 0..15
    int ty = tid >> 4;       // row group 0..15
    int row0 = blockIdx.x * BM;

    float acc[8][8];
#pragma unroll
    for (int i = 0; i < 8; ++i)
#pragma unroll
        for (int j = 0; j < 8; ++j) acc[i][j] = 0.f;

    for (int pass = 0; pass < 2; ++pass) {
        const float* A = pass ? A2 : A1;
        const float* W = pass ? W2 : W1;
        int K = pass ? K2 : K1;
        if (A == nullptr) continue;

        for (int k0 = 0; k0 < K; k0 += BK) {
            // load A tile (128 x 32) transposed into As[k][row]
#pragma unroll
            for (int i = 0; i < 4; ++i) {
                int s = tid + i * 256;
                int r = s >> 3;
                int cv = (s & 7) * 4;
                float4 v = make_float4(0.f, 0.f, 0.f, 0.f);
                int gr = row0 + r;
                if (gr < M) v = *(const float4*)(A + (size_t)gr * K + k0 + cv);
                As[cv + 0][r] = v.x;
                As[cv + 1][r] = v.y;
                As[cv + 2][r] = v.z;
                As[cv + 3][r] = v.w;
            }
            // load W tile (32 x 128)
#pragma unroll
            for (int i = 0; i < 4; ++i) {
                int s = tid + i * 256;
                int r = s >> 5;
                int cv = (s & 31) * 4;
                float4 v = *(const float4*)(W + (size_t)(k0 + r) * BN + cv);
                *(float4*)&Wt[r][cv] = v;
            }
            __syncthreads();

#pragma unroll
            for (int kk = 0; kk < BK; ++kk) {
                float a[8], b[8];
#pragma unroll
                for (int i = 0; i < 4; ++i) {
                    ((float4*)a)[0] = *(const float4*)&As[kk][ty * 8];
                    ((float4*)a)[1] = *(const float4*)&As[kk][ty * 8 + 4];
                    ((float4*)b)[0] = *(const float4*)&Wt[kk][tx * 8];
                    ((float4*)b)[1] = *(const float4*)&Wt[kk][tx * 8 + 4];
                    break;
                }
#pragma unroll
                for (int i = 0; i < 8; ++i)
#pragma unroll
                    for (int j = 0; j < 8; ++j)
                        acc[i][j] += a[i] * b[j];
            }
            __syncthreads();
        }
    }

    // epilogue
#pragma unroll
    for (int i = 0; i < 8; ++i) {
        int r = row0 + ty * 8 + i;
        if (r >= M) continue;
#pragma unroll
        for (int j = 0; j < 8; ++j) {
            int c = tx * 8 + j;
            float v = acc[i][j] + bias[c];
            if (do_relu) v = fmaxf(v, 0.f);
            C[(size_t)r * BN + c] = v;
        }
    }
}

// ---------------- dist layer0 : y = relu(e[M,5] @ W0[5,128] + b0) ----------------
#define D0_ROWS 16
__global__ void dist0_kernel(const float* __restrict__ e, const float* __restrict__ W0,
                             const float* __restrict__ b0, float* __restrict__ y, int M)
{
    __shared__ float ws[KD * HD];
    for (int i = threadIdx.x; i < KD * HD; i += blockDim.x) ws[i] = W0[i];
    __syncthreads();
    int c = threadIdx.x;            // 128 threads = 128 cols
    float bv = b0[c];
    int r0 = blockIdx.x * D0_ROWS;
    for (int rr = 0; rr < D0_ROWS; ++rr) {
        int r = r0 + rr;
        if (r >= M) return;
        float acc = bv;
#pragma unroll
        for (int k = 0; k < KD; ++k)
            acc += e[(size_t)r * KD + k] * ws[k * HD + c];
        y[(size_t)r * HD + c] = fmaxf(acc, 0.f);
    }
}

// ---------------- final: out = sigmoid([feat|dist] @ fW + fb) ----------------
__global__ void final_kernel(const float* __restrict__ feat, const float* __restrict__ dist,
                             const float* __restrict__ fW, const float* __restrict__ fb,
                             float* __restrict__ out, int M)
{
    __shared__ float w[2 * HD];
    if (threadIdx.x < 2 * HD) w[threadIdx.x] = fW[threadIdx.x];
    __syncthreads();
    int warp = (blockIdx.x * blockDim.x + threadIdx.x) >> 5;
    int lane = threadIdx.x & 31;
    if (warp >= M) return;
    float4 f = ((const float4*)(feat + (size_t)warp * HD))[lane];
    float4 d = ((const float4*)(dist + (size_t)warp * HD))[lane];
    float4 wf = ((const float4*)w)[lane];
    float4 wd = ((const float4*)w)[lane + 32];
    float sum = f.x * wf.x + f.y * wf.y + f.z * wf.z + f.w * wf.w
              + d.x * wd.x + d.y * wd.y + d.z * wd.z + d.w * wd.w;
#pragma unroll
    for (int off = 16; off > 0; off >>= 1)
        sum += __shfl_xor_sync(0xFFFFFFFF, sum, off);
    if (lane == 0) {
        float v = sum + fb[0];
        out[warp] = 1.0f / (1.0f + __expf(-v));
    }
}

// ---------------- launch ----------------
extern "C" void kernel_launch(void* const* d_in, const int* in_sizes, int n_in,
                              void* d_out, int out_size)
{
    const float* x          = (const float*)d_in[0];
    const void*  edge_index = d_in[1];
    const float* edge_attr  = (const float*)d_in[2];
    const float* pre_W      = (const float*)d_in[3];
    const float* pre_b      = (const float*)d_in[4];
    const float* c1_Ws      = (const float*)d_in[5];
    const float* c1_Wn      = (const float*)d_in[6];
    const float* c1_b       = (const float*)d_in[7];
    const float* c2_Ws      = (const float*)d_in[8];
    const float* c2_Wn      = (const float*)d_in[9];
    const float* c2_b       = (const float*)d_in[10];
    const float* np_W       = (const float*)d_in[11];
    const float* np_b       = (const float*)d_in[12];
    const float* d_W0       = (const float*)d_in[13];
    const float* d_b0       = (const float*)d_in[14];
    const float* d_W1       = (const float*)d_in[15];
    const float* d_b1       = (const float*)d_in[16];
    const float* d_W2       = (const float*)d_in[17];
    const float* d_b2       = (const float*)d_in[18];
    const float* d_W3       = (const float*)d_in[19];
    const float* d_b3       = (const float*)d_in[20];
    const float* final_W    = (const float*)d_in[21];
    const float* final_b    = (const float*)d_in[22];
    float* out = (float*)d_out;

    int M = NN;
    int E = in_sizes[1] / 2;
    if (E > EE) E = EE;

    float *hbuf, *h2buf, *aggbuf, *featbuf, *y0buf, *y1buf;
    cudaGetSymbolAddress((void**)&hbuf,    g_h);
    cudaGetSymbolAddress((void**)&h2buf,   g_h2);
    cudaGetSymbolAddress((void**)&aggbuf,  g_agg);
    cudaGetSymbolAddress((void**)&featbuf, g_feat);
    cudaGetSymbolAddress((void**)&y0buf,   g_y0);
    cudaGetSymbolAddress((void**)&y1buf,   g_y1);

    // --- CSR build ---
    detect_layout_kernel<<<1, 1>>>((const unsigned*)edge_index);
    extract_edges_kernel<<<(E + 255) / 256, 256>>>(edge_index, E);
    zero_counts_kernel<<<(M + 255) / 256, 256>>>(M);
    histogram_kernel<<<(E + 255) / 256, 256>>>(E);
    int nb = (M + 1023) / 1024;
    scan1_kernel<<<nb, 1024>>>(M);
    scan2_kernel<<<1, 32>>>(nb);
    scan3_kernel<<<(M + 255) / 256, 256>>>(M, E);
    scatter_csr_kernel<<<(E + 255) / 256, 256>>>(E);

    int gemm_grid = (M + BM - 1) / BM;

    // --- feat path ---
    // h = x @ pre_W + pre_b
    gemm_kernel<<<gemm_grid, 256>>>(x, pre_W, FIN, nullptr, nullptr, 0, pre_b, hbuf, M, 0);
    // agg = mean_agg(h)
    mean_agg_kernel<<<(M * 32 + 255) / 256, 256>>>(hbuf, aggbuf, M);
    // h2 = relu(h @ c1_Ws + agg @ c1_Wn + c1_b)
    gemm_kernel<<<gemm_grid, 256>>>(hbuf, c1_Ws, HD, aggbuf, c1_Wn, HD, c1_b, h2buf, M, 1);
    // agg = mean_agg(h2)
    mean_agg_kernel<<<(M * 32 + 255) / 256, 256>>>(h2buf, aggbuf, M);
    // h = relu(h2 @ c2_Ws + agg @ c2_Wn + c2_b)
    gemm_kernel<<<gemm_grid, 256>>>(h2buf, c2_Ws, HD, aggbuf, c2_Wn, HD, c2_b, hbuf, M, 1);
    // feat = h @ np_W + np_b
    gemm_kernel<<<gemm_grid, 256>>>(hbuf, np_W, HD, nullptr, nullptr, 0, np_b, featbuf, M, 0);

    // --- dist path ---
    dist0_kernel<<<(M + D0_ROWS - 1) / D0_ROWS, 128>>>(edge_attr, d_W0, d_b0, y0buf, M);
    gemm_kernel<<<gemm_grid, 256>>>(y0buf, d_W1, HD, nullptr, nullptr, 0, d_b1, y1buf, M, 1);
    gemm_kernel<<<gemm_grid, 256>>>(y1buf, d_W2, HD, nullptr, nullptr, 0, d_b2, y0buf, M, 1);
    gemm_kernel<<<gemm_grid, 256>>>(y0buf, d_W3, HD, nullptr, nullptr, 0, d_b3, y1buf, M, 0);

    // --- merge + final ---
    final_kernel<<<(M * 32 + 255) / 256, 256>>>(featbuf, y1buf, final_W, final_b, out, M);
}

// round 5
// speedup vs baseline: 2.1457x; 2.1457x over previous
#include <cuda_runtime.h>
#include <math.h>

// ---------------- problem constants ----------------
#define NN  100000
#define HD  128
#define EE  1600000
#define FIN 256
#define KD  5

// ---------------- scratch (static __device__, no allocation) ----------------
__device__ float g_h   [(size_t)NN * HD];
__device__ float g_h2  [(size_t)NN * HD];
__device__ float g_agg [(size_t)NN * HD];
__device__ float g_y0  [(size_t)NN * HD];
__device__ float g_y1  [(size_t)NN * HD];

__device__ int g_src[EE];
__device__ int g_dstv[EE];
__device__ int g_csr_src[EE];
__device__ int g_counts[NN];
__device__ int g_incl[NN];
__device__ int g_offs[NN + 1];
__device__ int g_cursor[NN];
__device__ int g_bsum[256];
__device__ int g_flag64;

// folded final-layer vectors: out = sigmoid(h_final . vfeat + y2 . vdist + cc)
__device__ float g_vfeat[HD];
__device__ float g_vdist[HD];
__device__ float g_cc;

// ---------------- edge-index dtype detection ----------------
// int64 little-endian with values < 2^31 => every odd 32-bit word of the first
// 32 elements is zero. For int32 data those words are random indices.
__global__ void detect_layout_kernel(const unsigned* __restrict__ p) {
    unsigned any = 0;
#pragma unroll
    for (int i = 1; i < 64; i += 2) any |= p[i];
    g_flag64 = (any == 0) ? 1 : 0;
}

__global__ void extract_edges_kernel(const void* __restrict__ edge_index, int E) {
    int i = blockIdx.x * blockDim.x + threadIdx.x;
    if (i >= E) return;
    if (g_flag64) {
        const long long* p = (const long long*)edge_index;
        g_src[i]  = (int)p[i];
        g_dstv[i] = (int)p[(size_t)E + i];
    } else {
        const int* p = (const int*)edge_index;
        g_src[i]  = p[i];
        g_dstv[i] = p[E + i];
    }
}

// ---------------- CSR build (counting sort by dst) ----------------
__global__ void zero_counts_kernel(int n) {
    int i = blockIdx.x * blockDim.x + threadIdx.x;
    if (i < n) g_counts[i] = 0;
}

__global__ void histogram_kernel(int E) {
    int i = blockIdx.x * blockDim.x + threadIdx.x;
    if (i < E) atomicAdd(&g_counts[g_dstv[i]], 1);
}

__global__ void scan1_kernel(int n) {
    __shared__ int s[1024];
    int i = blockIdx.x * 1024 + threadIdx.x;
    int v = (i < n) ? g_counts[i] : 0;
    s[threadIdx.x] = v;
    __syncthreads();
#pragma unroll
    for (int off = 1; off < 1024; off <<= 1) {
        int t = (threadIdx.x >= off) ? s[threadIdx.x - off] : 0;
        __syncthreads();
        s[threadIdx.x] += t;
        __syncthreads();
    }
    if (i < n) g_incl[i] = s[threadIdx.x];
    if (threadIdx.x == 1023) g_bsum[blockIdx.x] = s[1023];
}

__global__ void scan2_kernel(int nb) {
    if (threadIdx.x == 0 && blockIdx.x == 0) {
        int run = 0;
        for (int i = 0; i < nb; ++i) {
            int v = g_bsum[i];
            g_bsum[i] = run;
            run += v;
        }
    }
}

__global__ void scan3_kernel(int n, int E) {
    int i = blockIdx.x * blockDim.x + threadIdx.x;
    if (i >= n) return;
    int off = g_bsum[i >> 10] + g_incl[i] - g_counts[i];
    g_offs[i] = off;
    g_cursor[i] = off;
    if (i == n - 1) g_offs[n] = E;
}

__global__ void scatter_csr_kernel(int E) {
    int i = blockIdx.x * blockDim.x + threadIdx.x;
    if (i >= E) return;
    int d = g_dstv[i];
    int p = atomicAdd(&g_cursor[d], 1);
    g_csr_src[p] = g_src[i];
}

// ---------------- mean aggregation: one warp per node, 4-wide gather ----------------
__global__ void mean_agg_kernel(const float* __restrict__ h, float* __restrict__ agg, int n) {
    int warp = (blockIdx.x * blockDim.x + threadIdx.x) >> 5;
    int lane = threadIdx.x & 31;
    if (warp >= n) return;
    int s = g_offs[warp];
    int e = g_offs[warp + 1];
    float4 acc = make_float4(0.f, 0.f, 0.f, 0.f);
    int i = s;
    for (; i + 4 <= e; i += 4) {
        int s0 = __ldg(&g_csr_src[i]);
        int s1 = __ldg(&g_csr_src[i + 1]);
        int s2 = __ldg(&g_csr_src[i + 2]);
        int s3 = __ldg(&g_csr_src[i + 3]);
        float4 v0 = ((const float4*)(h + (size_t)s0 * HD))[lane];
        float4 v1 = ((const float4*)(h + (size_t)s1 * HD))[lane];
        float4 v2 = ((const float4*)(h + (size_t)s2 * HD))[lane];
        float4 v3 = ((const float4*)(h + (size_t)s3 * HD))[lane];
        acc.x += v0.x + v1.x + v2.x + v3.x;
        acc.y += v0.y + v1.y + v2.y + v3.y;
        acc.z += v0.z + v1.z + v2.z + v3.z;
        acc.w += v0.w + v1.w + v2.w + v3.w;
    }
    for (; i < e; ++i) {
        int s0 = __ldg(&g_csr_src[i]);
        float4 v0 = ((const float4*)(h + (size_t)s0 * HD))[lane];
        acc.x += v0.x; acc.y += v0.y; acc.z += v0.z; acc.w += v0.w;
    }
    float inv = 1.0f / (float)max(e - s, 1);
    acc.x *= inv; acc.y *= inv; acc.z *= inv; acc.w *= inv;
    ((float4*)(agg + (size_t)warp * HD))[lane] = acc;
}

// ---------------- TF32 tensor-core GEMM ----------------
// C[M,128] = act(A1@W1 + A2@W2 + bias), A row-major [M,K], W row-major [K,128]
#define BM 128
#define BN 128
#define BK 32
#define SMP 132   // padded shared stride

__device__ __forceinline__ float to_tf32(float x) {
    unsigned u;
    asm("cvt.rna.tf32.f32 %0, %1;" : "=r"(u) : "f"(x));
    return __uint_as_float(u);
}

__device__ __forceinline__ void mma_tf32(float* c, const unsigned* a, const unsigned* b) {
    asm volatile(
        "mma.sync.aligned.m16n8k8.row.col.f32.tf32.tf32.f32 "
        "{%0,%1,%2,%3}, {%4,%5,%6,%7}, {%8,%9}, {%0,%1,%2,%3};"
        : "+f"(c[0]), "+f"(c[1]), "+f"(c[2]), "+f"(c[3])
        : "r"(a[0]), "r"(a[1]), "r"(a[2]), "r"(a[3]), "r"(b[0]), "r"(b[1]));
}

__global__ void __launch_bounds__(256) tf32_gemm_kernel(
    const float* __restrict__ A1, const float* __restrict__ W1, int K1,
    const float* __restrict__ A2, const float* __restrict__ W2, int K2,
    const float* __restrict__ bias, float* __restrict__ C, int M, int do_relu)
{
    __shared__ float As[BK][SMP];   // [k][m], tf32-rounded
    __shared__ float Bs[BK][SMP];   // [k][n], tf32-rounded

    int tid = threadIdx.x;
    int lane = tid & 31;
    int warp = tid >> 5;
    int wm = (warp >> 2) * 64;   // warp row offset (2 warp-rows)
    int wn = (warp & 3) * 32;    // warp col offset (4 warp-cols)
    int row0 = blockIdx.x * BM;

    float acc[4][4][4];
#pragma unroll
    for (int i = 0; i < 4; ++i)
#pragma unroll
        for (int j = 0; j < 4; ++j)
#pragma unroll
            for (int k = 0; k < 4; ++k) acc[i][j][k] = 0.f;

    for (int pass = 0; pass < 2; ++pass) {
        const float* A = pass ? A2 : A1;
        const float* W = pass ? W2 : W1;
        int K = pass ? K2 : K1;
        if (A == nullptr) continue;

        for (int k0 = 0; k0 < K; k0 += BK) {
            // load A tile (128 rows x 32 k), transpose into As[k][m]
#pragma unroll
            for (int i = 0; i < 4; ++i) {
                int s = tid + i * 256;
                int r = s >> 3;
                int cv = (s & 7) * 4;
                float4 v = make_float4(0.f, 0.f, 0.f, 0.f);
                int gr = row0 + r;
                if (gr < M) v = *(const float4*)(A + (size_t)gr * K + k0 + cv);
                As[cv + 0][r] = to_tf32(v.x);
                As[cv + 1][r] = to_tf32(v.y);
                As[cv + 2][r] = to_tf32(v.z);
                As[cv + 3][r] = to_tf32(v.w);
            }
            // load W tile (32 k x 128 n) into Bs[k][n]
#pragma unroll
            for (int i = 0; i < 4; ++i) {
                int s = tid + i * 256;
                int r = s >> 5;
                int cv = (s & 31) * 4;
                float4 v = *(const float4*)(W + (size_t)(k0 + r) * BN + cv);
                Bs[r][cv + 0] = to_tf32(v.x);
                Bs[r][cv + 1] = to_tf32(v.y);
                Bs[r][cv + 2] = to_tf32(v.z);
                Bs[r][cv + 3] = to_tf32(v.w);
            }
            __syncthreads();

#pragma unroll
            for (int kk = 0; kk < BK; kk += 8) {
                unsigned a[4][4], b[4][2];
                int kq = kk + (lane & 3);
                int g = lane >> 2;
#pragma unroll
                for (int fm = 0; fm < 4; ++fm) {
                    int m = wm + fm * 16 + g;
                    a[fm][0] = __float_as_uint(As[kq][m]);
                    a[fm][1] = __float_as_uint(As[kq][m + 8]);
                    a[fm][2] = __float_as_uint(As[kq + 4][m]);
                    a[fm][3] = __float_as_uint(As[kq + 4][m + 8]);
                }
#pragma unroll
                for (int fn = 0; fn < 4; ++fn) {
                    int n = wn + fn * 8 + g;
                    b[fn][0] = __float_as_uint(Bs[kq][n]);
                    b[fn][1] = __float_as_uint(Bs[kq + 4][n]);
                }
#pragma unroll
                for (int fm = 0; fm < 4; ++fm)
#pragma unroll
                    for (int fn = 0; fn < 4; ++fn)
                        mma_tf32(acc[fm][fn], a[fm], b[fn]);
            }
            __syncthreads();
        }
    }

    // epilogue: c0,c1 at (row, 2q),(row, 2q+1); c2,c3 at row+8
    int g = lane >> 2;
    int q = lane & 3;
#pragma unroll
    for (int fm = 0; fm < 4; ++fm) {
#pragma unroll
        for (int fn = 0; fn < 4; ++fn) {
            int r = row0 + wm + fm * 16 + g;
            int c = wn + fn * 8 + (q << 1);
            float b0 = bias[c], b1 = bias[c + 1];
            float v0 = acc[fm][fn][0] + b0;
            float v1 = acc[fm][fn][1] + b1;
            float v2 = acc[fm][fn][2] + b0;
            float v3 = acc[fm][fn][3] + b1;
            if (do_relu) {
                v0 = fmaxf(v0, 0.f); v1 = fmaxf(v1, 0.f);
                v2 = fmaxf(v2, 0.f); v3 = fmaxf(v3, 0.f);
            }
            if (r < M)     *(float2*)(C + (size_t)r * BN + c)       = make_float2(v0, v1);
            if (r + 8 < M) *(float2*)(C + (size_t)(r + 8) * BN + c) = make_float2(v2, v3);
        }
    }
}

// ---------------- dist layer0 : y = relu(e[M,5] @ W0[5,128] + b0) ----------------
#define D0_ROWS 16
__global__ void dist0_kernel(const float* __restrict__ e, const float* __restrict__ W0,
                             const float* __restrict__ b0, float* __restrict__ y, int M)
{
    __shared__ float ws[KD * HD];
    for (int i = threadIdx.x; i < KD * HD; i += blockDim.x) ws[i] = W0[i];
    __syncthreads();
    int c = threadIdx.x;
    float bv = b0[c];
    int r0 = blockIdx.x * D0_ROWS;
    for (int rr = 0; rr < D0_ROWS; ++rr) {
        int r = r0 + rr;
        if (r >= M) return;
        float acc = bv;
#pragma unroll
        for (int k = 0; k < KD; ++k)
            acc += e[(size_t)r * KD + k] * ws[k * HD + c];
        y[(size_t)r * HD + c] = fmaxf(acc, 0.f);
    }
}

// ---------------- fold nodepost + d3 + final_W into two 128-vectors ----------------
// feat@fW_top = h @ (np_W @ fW_top); dist@fW_bot = y2 @ (d_W3 @ fW_bot)
__global__ void fold_final_kernel(
    const float* __restrict__ np_W, const float* __restrict__ np_b,
    const float* __restrict__ d_W3, const float* __restrict__ d_b3,
    const float* __restrict__ fW, const float* __restrict__ fb)
{
    int j = threadIdx.x;  // 128
    float vf = 0.f, vd = 0.f;
#pragma unroll 8
    for (int k = 0; k < HD; ++k) {
        vf += np_W[j * HD + k] * fW[k];
        vd += d_W3[j * HD + k] * fW[HD + k];
    }
    g_vfeat[j] = vf;
    g_vdist[j] = vd;
    if (j == 0) {
        float c = fb[0];
        for (int k = 0; k < HD; ++k)
            c += np_b[k] * fW[k] + d_b3[k] * fW[HD + k];
        g_cc = c;
    }
}

// ---------------- fused final: out = sigmoid(h.vfeat + y2.vdist + cc) ----------------
__global__ void final_dot_kernel(const float* __restrict__ hfin, const float* __restrict__ y2,
                                 float* __restrict__ out, int M)
{
    __shared__ float w[2 * HD];
    if (threadIdx.x < HD)          w[threadIdx.x]     = g_vfeat[threadIdx.x];
    else if (threadIdx.x < 2 * HD) w[threadIdx.x]     = g_vdist[threadIdx.x - HD];
    __syncthreads();
    int warp = (blockIdx.x * blockDim.x + threadIdx.x) >> 5;
    int lane = threadIdx.x & 31;
    if (warp >= M) return;
    float4 f = ((const float4*)(hfin + (size_t)warp * HD))[lane];
    float4 d = ((const float4*)(y2 + (size_t)warp * HD))[lane];
    float4 wf = ((const float4*)w)[lane];
    float4 wd = ((const float4*)w)[lane + 32];
    float sum = f.x * wf.x + f.y * wf.y + f.z * wf.z + f.w * wf.w
              + d.x * wd.x + d.y * wd.y + d.z * wd.z + d.w * wd.w;
#pragma unroll
    for (int off = 16; off > 0; off >>= 1)
        sum += __shfl_xor_sync(0xFFFFFFFF, sum, off);
    if (lane == 0) {
        float v = sum + g_cc;
        out[warp] = 1.0f / (1.0f + __expf(-v));
    }
}

// ---------------- launch ----------------
extern "C" void kernel_launch(void* const* d_in, const int* in_sizes, int n_in,
                              void* d_out, int out_size)
{
    const float* x          = (const float*)d_in[0];
    const void*  edge_index = d_in[1];
    const float* edge_attr  = (const float*)d_in[2];
    const float* pre_W      = (const float*)d_in[3];
    const float* pre_b      = (const float*)d_in[4];
    const float* c1_Ws      = (const float*)d_in[5];
    const float* c1_Wn      = (const float*)d_in[6];
    const float* c1_b       = (const float*)d_in[7];
    const float* c2_Ws      = (const float*)d_in[8];
    const float* c2_Wn      = (const float*)d_in[9];
    const float* c2_b       = (const float*)d_in[10];
    const float* np_W       = (const float*)d_in[11];
    const float* np_b       = (const float*)d_in[12];
    const float* d_W0       = (const float*)d_in[13];
    const float* d_b0       = (const float*)d_in[14];
    const float* d_W1       = (const float*)d_in[15];
    const float* d_b1       = (const float*)d_in[16];
    const float* d_W2       = (const float*)d_in[17];
    const float* d_b2       = (const float*)d_in[18];
    const float* d_W3       = (const float*)d_in[19];
    const float* d_b3       = (const float*)d_in[20];
    const float* final_W    = (const float*)d_in[21];
    const float* final_b    = (const float*)d_in[22];
    float* out = (float*)d_out;

    int M = NN;
    int E = in_sizes[1] / 2;
    if (E > EE) E = EE;

    float *hbuf, *h2buf, *aggbuf, *y0buf, *y1buf;
    cudaGetSymbolAddress((void**)&hbuf,   g_h);
    cudaGetSymbolAddress((void**)&h2buf,  g_h2);
    cudaGetSymbolAddress((void**)&aggbuf, g_agg);
    cudaGetSymbolAddress((void**)&y0buf,  g_y0);
    cudaGetSymbolAddress((void**)&y1buf,  g_y1);

    // --- CSR build ---
    detect_layout_kernel<<<1, 1>>>((const unsigned*)edge_index);
    extract_edges_kernel<<<(E + 255) / 256, 256>>>(edge_index, E);
    zero_counts_kernel<<<(M + 255) / 256, 256>>>(M);
    histogram_kernel<<<(E + 255) / 256, 256>>>(E);
    int nb = (M + 1023) / 1024;
    scan1_kernel<<<nb, 1024>>>(M);
    scan2_kernel<<<1, 32>>>(nb);
    scan3_kernel<<<(M + 255) / 256, 256>>>(M, E);
    scatter_csr_kernel<<<(E + 255) / 256, 256>>>(E);

    // --- fold final layers ---
    fold_final_kernel<<<1, 128>>>(np_W, np_b, d_W3, d_b3, final_W, final_b);

    int gemm_grid = (M + BM - 1) / BM;

    // --- feat path ---
    tf32_gemm_kernel<<<gemm_grid, 256>>>(x, pre_W, FIN, nullptr, nullptr, 0, pre_b, hbuf, M, 0);
    mean_agg_kernel<<<(M * 32 + 255) / 256, 256>>>(hbuf, aggbuf, M);
    tf32_gemm_kernel<<<gemm_grid, 256>>>(hbuf, c1_Ws, HD, aggbuf, c1_Wn, HD, c1_b, h2buf, M, 1);
    mean_agg_kernel<<<(M * 32 + 255) / 256, 256>>>(h2buf, aggbuf, M);
    tf32_gemm_kernel<<<gemm_grid, 256>>>(h2buf, c2_Ws, HD, aggbuf, c2_Wn, HD, c2_b, hbuf, M, 1);

    // --- dist path ---
    dist0_kernel<<<(M + D0_ROWS - 1) / D0_ROWS, 128>>>(edge_attr, d_W0, d_b0, y0buf, M);
    tf32_gemm_kernel<<<gemm_grid, 256>>>(y0buf, d_W1, HD, nullptr, nullptr, 0, d_b1, y1buf, M, 1);
    tf32_gemm_kernel<<<gemm_grid, 256>>>(y1buf, d_W2, HD, nullptr, nullptr, 0, d_b2, y0buf, M, 1);

    // --- fused final ---
    final_dot_kernel<<<(M * 32 + 255) / 256, 256>>>(hbuf, y0buf, out, M);
}

// round 6
// speedup vs baseline: 2.4727x; 1.1524x over previous
#include <cuda_runtime.h>
#include <cuda_bf16.h>
#include <math.h>

// ---------------- problem constants ----------------
#define NN  100000
#define HD  128
#define EE  1600000
#define FIN 256
#define KD  5

// ---------------- scratch (static __device__, no allocation) ----------------
__device__ float g_h   [(size_t)NN * HD];
__device__ float g_h2  [(size_t)NN * HD];
__device__ float g_agg [(size_t)NN * HD];
__device__ float g_y0  [(size_t)NN * HD];
__device__ float g_y1  [(size_t)NN * HD];
__device__ __nv_bfloat16 g_hb16[(size_t)NN * HD];

__device__ int g_src[EE];
__device__ int g_dstv[EE];
__device__ int g_csr_src[EE];
__device__ int g_counts[NN];
__device__ int g_incl[NN];
__device__ int g_offs[NN + 1];
__device__ int g_cursor[NN];
__device__ int g_bsum[256];
__device__ int g_flag64;

// folded final-layer vectors: out = sigmoid(h_final . vfeat + y2 . vdist + cc)
__device__ float g_vfeat[HD];
__device__ float g_vdist[HD];
__device__ float g_cc;

// ---------------- edge-index dtype detection ----------------
__global__ void detect_layout_kernel(const unsigned* __restrict__ p) {
    unsigned any = 0;
#pragma unroll
    for (int i = 1; i < 64; i += 2) any |= p[i];
    g_flag64 = (any == 0) ? 1 : 0;
}

// merged: zero counts (i < n) + extract edges (i < E)
__global__ void extract_zero_kernel(const void* __restrict__ edge_index, int E, int n) {
    int i = blockIdx.x * blockDim.x + threadIdx.x;
    if (i < n) g_counts[i] = 0;
    if (i >= E) return;
    if (g_flag64) {
        const long long* p = (const long long*)edge_index;
        g_src[i]  = (int)p[i];
        g_dstv[i] = (int)p[(size_t)E + i];
    } else {
        const int* p = (const int*)edge_index;
        g_src[i]  = p[i];
        g_dstv[i] = p[E + i];
    }
}

// ---------------- CSR build (counting sort by dst) ----------------
__global__ void histogram_kernel(int E) {
    int i = blockIdx.x * blockDim.x + threadIdx.x;
    if (i < E) atomicAdd(&g_counts[g_dstv[i]], 1);
}

__global__ void scan1_kernel(int n) {
    __shared__ int s[1024];
    int i = blockIdx.x * 1024 + threadIdx.x;
    int v = (i < n) ? g_counts[i] : 0;
    s[threadIdx.x] = v;
    __syncthreads();
#pragma unroll
    for (int off = 1; off < 1024; off <<= 1) {
        int t = (threadIdx.x >= off) ? s[threadIdx.x - off] : 0;
        __syncthreads();
        s[threadIdx.x] += t;
        __syncthreads();
    }
    if (i < n) g_incl[i] = s[threadIdx.x];
    if (threadIdx.x == 1023) g_bsum[blockIdx.x] = s[1023];
}

__global__ void scan2_kernel(int nb) {
    if (threadIdx.x == 0 && blockIdx.x == 0) {
        int run = 0;
        for (int i = 0; i < nb; ++i) {
            int v = g_bsum[i];
            g_bsum[i] = run;
            run += v;
        }
    }
}

__global__ void scan3_kernel(int n, int E) {
    int i = blockIdx.x * blockDim.x + threadIdx.x;
    if (i >= n) return;
    int off = g_bsum[i >> 10] + g_incl[i] - g_counts[i];
    g_offs[i] = off;
    g_cursor[i] = off;
    if (i == n - 1) g_offs[n] = E;
}

__global__ void scatter_csr_kernel(int E) {
    int i = blockIdx.x * blockDim.x + threadIdx.x;
    if (i >= E) return;
    int d = g_dstv[i];
    int p = atomicAdd(&g_cursor[d], 1);
    g_csr_src[p] = g_src[i];
}

// ---------------- mean aggregation: bf16 gather, one warp per node ----------------
__global__ void mean_agg_kernel(const __nv_bfloat16* __restrict__ h16,
                                float* __restrict__ agg, int n) {
    int warp = (blockIdx.x * blockDim.x + threadIdx.x) >> 5;
    int lane = threadIdx.x & 31;
    if (warp >= n) return;
    int s = g_offs[warp];
    int e = g_offs[warp + 1];
    float a0 = 0.f, a1 = 0.f, a2 = 0.f, a3 = 0.f;
    int i = s;
    for (; i + 4 <= e; i += 4) {
        int s0 = __ldg(&g_csr_src[i]);
        int s1 = __ldg(&g_csr_src[i + 1]);
        int s2 = __ldg(&g_csr_src[i + 2]);
        int s3 = __ldg(&g_csr_src[i + 3]);
        uint2 u0 = ((const uint2*)(h16 + (size_t)s0 * HD))[lane];
        uint2 u1 = ((const uint2*)(h16 + (size_t)s1 * HD))[lane];
        uint2 u2 = ((const uint2*)(h16 + (size_t)s2 * HD))[lane];
        uint2 u3 = ((const uint2*)(h16 + (size_t)s3 * HD))[lane];
        float2 p;
        p = __bfloat1622float2(*(__nv_bfloat162*)&u0.x); a0 += p.x; a1 += p.y;
        p = __bfloat1622float2(*(__nv_bfloat162*)&u0.y); a2 += p.x; a3 += p.y;
        p = __bfloat1622float2(*(__nv_bfloat162*)&u1.x); a0 += p.x; a1 += p.y;
        p = __bfloat1622float2(*(__nv_bfloat162*)&u1.y); a2 += p.x; a3 += p.y;
        p = __bfloat1622float2(*(__nv_bfloat162*)&u2.x); a0 += p.x; a1 += p.y;
        p = __bfloat1622float2(*(__nv_bfloat162*)&u2.y); a2 += p.x; a3 += p.y;
        p = __bfloat1622float2(*(__nv_bfloat162*)&u3.x); a0 += p.x; a1 += p.y;
        p = __bfloat1622float2(*(__nv_bfloat162*)&u3.y); a2 += p.x; a3 += p.y;
    }
    for (; i < e; ++i) {
        int s0 = __ldg(&g_csr_src[i]);
        uint2 u0 = ((const uint2*)(h16 + (size_t)s0 * HD))[lane];
        float2 p;
        p = __bfloat1622float2(*(__nv_bfloat162*)&u0.x); a0 += p.x; a1 += p.y;
        p = __bfloat1622float2(*(__nv_bfloat162*)&u0.y); a2 += p.x; a3 += p.y;
    }
    float inv = 1.0f / (float)max(e - s, 1);
    float4 r = make_float4(a0 * inv, a1 * inv, a2 * inv, a3 * inv);
    ((float4*)(agg + (size_t)warp * HD))[lane] = r;
}

// ---------------- TF32 tensor-core GEMM, cp.async 2-stage pipeline ----------------
// C[M,128] = act(A1@W1 + A2@W2 + bias), A row-major [M,K], W row-major [K,128]
#define BM 128
#define BN 128
#define BK 32
#define SA 36    // As row stride (floats): bank = (4g+q) -> conflict-free
#define SB 136   // Bs row stride (floats): bank = (8q+g) -> conflict-free
#define STAGE_FLOATS 8960          // 128*36 + 32*136
#define GEMM_SMEM   (2 * STAGE_FLOATS * 4)   // 71680 B

__device__ __forceinline__ unsigned smem_u32p(const void* p) {
    return (unsigned)__cvta_generic_to_shared(p);
}

__device__ __forceinline__ void cp_async16(unsigned dst, const void* src, int pred) {
    asm volatile("cp.async.cg.shared.global [%0], [%1], 16, %2;\n"
                 :: "r"(dst), "l"(src), "r"(pred ? 16 : 0));
}

__device__ __forceinline__ void gemm_load_tile(
    float* As, float* Bs, const float* __restrict__ A, const float* __restrict__ W,
    int K, int k0, int row0, int M, int tid)
{
    // A tile: 128 rows x 32 k (128 B/row) = 1024 x 16B chunks, layout [m][k]
#pragma unroll
    for (int i = 0; i < 4; ++i) {
        int c = tid + i * 256;
        int r = c >> 3;
        int off = (c & 7) * 4;            // float offset within row
        int gr = row0 + r;
        cp_async16(smem_u32p(As + r * SA + off),
                   A + (size_t)gr * K + k0 + off, gr < M);
    }
    // W tile: 32 rows x 128 n (512 B/row) = 1024 x 16B chunks, layout [k][n]
#pragma unroll
    for (int i = 0; i < 4; ++i) {
        int c = tid + i * 256;
        int r = c >> 5;
        int off = (c & 31) * 4;
        cp_async16(smem_u32p(Bs + r * SB + off),
                   W + (size_t)(k0 + r) * BN + off, 1);
    }
    asm volatile("cp.async.commit_group;\n" ::);
}

__device__ __forceinline__ void mma_tf32(float* c, const unsigned* a, const unsigned* b) {
    asm volatile(
        "mma.sync.aligned.m16n8k8.row.col.f32.tf32.tf32.f32 "
        "{%0,%1,%2,%3}, {%4,%5,%6,%7}, {%8,%9}, {%0,%1,%2,%3};"
        : "+f"(c[0]), "+f"(c[1]), "+f"(c[2]), "+f"(c[3])
        : "r"(a[0]), "r"(a[1]), "r"(a[2]), "r"(a[3]), "r"(b[0]), "r"(b[1]));
}

__global__ void __launch_bounds__(256) tf32_gemm_kernel(
    const float* __restrict__ A1, const float* __restrict__ W1, int K1,
    const float* __restrict__ A2, const float* __restrict__ W2, int K2,
    const float* __restrict__ bias, float* __restrict__ C,
    __nv_bfloat16* __restrict__ C16, int M, int do_relu)
{
    extern __shared__ float sm[];
    float* AsB[2] = { sm,                sm + STAGE_FLOATS };
    float* BsB[2] = { sm + 128 * SA,     sm + STAGE_FLOATS + 128 * SA };

    int tid = threadIdx.x;
    int lane = tid & 31;
    int warp = tid >> 5;
    int wm = (warp >> 2) * 64;
    int wn = (warp & 3) * 32;
    int row0 = blockIdx.x * BM;
    int g = lane >> 2;
    int q = lane & 3;

    float acc[4][4][4];
#pragma unroll
    for (int i = 0; i < 4; ++i)
#pragma unroll
        for (int j = 0; j < 4; ++j)
#pragma unroll
            for (int k = 0; k < 4; ++k) acc[i][j][k] = 0.f;

    int nt1 = K1 >> 5;
    int nt2 = A2 ? (K2 >> 5) : 0;
    int total = nt1 + nt2;

    // prologue: tile 0 (pass 0 always exists)
    gemm_load_tile(AsB[0], BsB[0], A1, W1, K1, 0, row0, M, tid);

    for (int t = 0; t < total; ++t) {
        if (t + 1 < total) {
            int p = (t + 1 >= nt1);
            const float* A = p ? A2 : A1;
            const float* W = p ? W2 : W1;
            int K = p ? K2 : K1;
            int k0 = ((t + 1) - (p ? nt1 : 0)) * BK;
            gemm_load_tile(AsB[(t + 1) & 1], BsB[(t + 1) & 1], A, W, K, k0, row0, M, tid);
            asm volatile("cp.async.wait_group 1;\n" ::);
        } else {
            asm volatile("cp.async.wait_group 0;\n" ::);
        }
        __syncthreads();

        const float* As = AsB[t & 1];
        const float* Bs = BsB[t & 1];
#pragma unroll
        for (int kk = 0; kk < BK; kk += 8) {
            int kq = kk + q;
            unsigned a[4][4], b[4][2];
#pragma unroll
            for (int fm = 0; fm < 4; ++fm) {
                int m = wm + fm * 16 + g;
                a[fm][0] = __float_as_uint(As[m * SA + kq]);
                a[fm][1] = __float_as_uint(As[(m + 8) * SA + kq]);
                a[fm][2] = __float_as_uint(As[m * SA + kq + 4]);
                a[fm][3] = __float_as_uint(As[(m + 8) * SA + kq + 4]);
            }
#pragma unroll
            for (int fn = 0; fn < 4; ++fn) {
                int n = wn + fn * 8 + g;
                b[fn][0] = __float_as_uint(Bs[kq * SB + n]);
                b[fn][1] = __float_as_uint(Bs[(kq + 4) * SB + n]);
            }
#pragma unroll
            for (int fm = 0; fm < 4; ++fm)
#pragma unroll
                for (int fn = 0; fn < 4; ++fn)
                    mma_tf32(acc[fm][fn], a[fm], b[fn]);
        }
        __syncthreads();
    }

    // epilogue: c0,c1 at (row, 2q),(row, 2q+1); c2,c3 at row+8
#pragma unroll
    for (int fm = 0; fm < 4; ++fm) {
#pragma unroll
        for (int fn = 0; fn < 4; ++fn) {
            int r = row0 + wm + fm * 16 + g;
            int c = wn + fn * 8 + (q << 1);
            float b0 = bias[c], b1 = bias[c + 1];
            float v0 = acc[fm][fn][0] + b0;
            float v1 = acc[fm][fn][1] + b1;
            float v2 = acc[fm][fn][2] + b0;
            float v3 = acc[fm][fn][3] + b1;
            if (do_relu) {
                v0 = fmaxf(v0, 0.f); v1 = fmaxf(v1, 0.f);
                v2 = fmaxf(v2, 0.f); v3 = fmaxf(v3, 0.f);
            }
            if (r < M) {
                *(float2*)(C + (size_t)r * BN + c) = make_float2(v0, v1);
                if (C16)
                    *(__nv_bfloat162*)(C16 + (size_t)r * BN + c) =
                        __float22bfloat162_rn(make_float2(v0, v1));
            }
            if (r + 8 < M) {
                *(float2*)(C + (size_t)(r + 8) * BN + c) = make_float2(v2, v3);
                if (C16)
                    *(__nv_bfloat162*)(C16 + (size_t)(r + 8) * BN + c) =
                        __float22bfloat162_rn(make_float2(v2, v3));
            }
        }
    }
}

// ---------------- dist layer0 : y = relu(e[M,5] @ W0[5,128] + b0) ----------------
#define D0_ROWS 16
__global__ void dist0_kernel(const float* __restrict__ e, const float* __restrict__ W0,
                             const float* __restrict__ b0, float* __restrict__ y, int M)
{
    __shared__ float ws[KD * HD];
    for (int i = threadIdx.x; i < KD * HD; i += blockDim.x) ws[i] = W0[i];
    __syncthreads();
    int c = threadIdx.x;
    float bv = b0[c];
    int r0 = blockIdx.x * D0_ROWS;
    for (int rr = 0; rr < D0_ROWS; ++rr) {
        int r = r0 + rr;
        if (r >= M) return;
        float acc = bv;
#pragma unroll
        for (int k = 0; k < KD; ++k)
            acc += e[(size_t)r * KD + k] * ws[k * HD + c];
        y[(size_t)r * HD + c] = fmaxf(acc, 0.f);
    }
}

// ---------------- fold nodepost + d3 + final_W into two 128-vectors ----------------
__global__ void fold_final_kernel(
    const float* __restrict__ np_W, const float* __restrict__ np_b,
    const float* __restrict__ d_W3, const float* __restrict__ d_b3,
    const float* __restrict__ fW, const float* __restrict__ fb)
{
    int j = threadIdx.x;  // 128
    float vf = 0.f, vd = 0.f;
#pragma unroll 8
    for (int k = 0; k < HD; ++k) {
        vf += np_W[j * HD + k] * fW[k];
        vd += d_W3[j * HD + k] * fW[HD + k];
    }
    g_vfeat[j] = vf;
    g_vdist[j] = vd;
    if (j == 0) {
        float c = fb[0];
        for (int k = 0; k < HD; ++k)
            c += np_b[k] * fW[k] + d_b3[k] * fW[HD + k];
        g_cc = c;
    }
}

// ---------------- fused final: out = sigmoid(h.vfeat + y2.vdist + cc) ----------------
__global__ void final_dot_kernel(const float* __restrict__ hfin, const float* __restrict__ y2,
                                 float* __restrict__ out, int M)
{
    __shared__ float w[2 * HD];
    if (threadIdx.x < HD)          w[threadIdx.x] = g_vfeat[threadIdx.x];
    else if (threadIdx.x < 2 * HD) w[threadIdx.x] = g_vdist[threadIdx.x - HD];
    __syncthreads();
    int warp = (blockIdx.x * blockDim.x + threadIdx.x) >> 5;
    int lane = threadIdx.x & 31;
    if (warp >= M) return;
    float4 f = ((const float4*)(hfin + (size_t)warp * HD))[lane];
    float4 d = ((const float4*)(y2 + (size_t)warp * HD))[lane];
    float4 wf = ((const float4*)w)[lane];
    float4 wd = ((const float4*)w)[lane + 32];
    float sum = f.x * wf.x + f.y * wf.y + f.z * wf.z + f.w * wf.w
              + d.x * wd.x + d.y * wd.y + d.z * wd.z + d.w * wd.w;
#pragma unroll
    for (int off = 16; off > 0; off >>= 1)
        sum += __shfl_xor_sync(0xFFFFFFFF, sum, off);
    if (lane == 0) {
        float v = sum + g_cc;
        out[warp] = 1.0f / (1.0f + __expf(-v));
    }
}

// ---------------- launch ----------------
extern "C" void kernel_launch(void* const* d_in, const int* in_sizes, int n_in,
                              void* d_out, int out_size)
{
    const float* x          = (const float*)d_in[0];
    const void*  edge_index = d_in[1];
    const float* edge_attr  = (const float*)d_in[2];
    const float* pre_W      = (const float*)d_in[3];
    const float* pre_b      = (const float*)d_in[4];
    const float* c1_Ws      = (const float*)d_in[5];
    const float* c1_Wn      = (const float*)d_in[6];
    const float* c1_b       = (const float*)d_in[7];
    const float* c2_Ws      = (const float*)d_in[8];
    const float* c2_Wn      = (const float*)d_in[9];
    const float* c2_b       = (const float*)d_in[10];
    const float* np_W       = (const float*)d_in[11];
    const float* np_b       = (const float*)d_in[12];
    const float* d_W0       = (const float*)d_in[13];
    const float* d_b0       = (const float*)d_in[14];
    const float* d_W1       = (const float*)d_in[15];
    const float* d_b1       = (const float*)d_in[16];
    const float* d_W2       = (const float*)d_in[17];
    const float* d_b2       = (const float*)d_in[18];
    const float* d_W3       = (const float*)d_in[19];
    const float* d_b3       = (const float*)d_in[20];
    const float* final_W    = (const float*)d_in[21];
    const float* final_b    = (const float*)d_in[22];
    float* out = (float*)d_out;

    int M = NN;
    int E = in_sizes[1] / 2;
    if (E > EE) E = EE;

    float *hbuf, *h2buf, *aggbuf, *y0buf, *y1buf;
    __nv_bfloat16* hb16;
    cudaGetSymbolAddress((void**)&hbuf,   g_h);
    cudaGetSymbolAddress((void**)&h2buf,  g_h2);
    cudaGetSymbolAddress((void**)&aggbuf, g_agg);
    cudaGetSymbolAddress((void**)&y0buf,  g_y0);
    cudaGetSymbolAddress((void**)&y1buf,  g_y1);
    cudaGetSymbolAddress((void**)&hb16,   g_hb16);

    cudaFuncSetAttribute(tf32_gemm_kernel,
                         cudaFuncAttributeMaxDynamicSharedMemorySize, GEMM_SMEM);

    // --- CSR build ---
    detect_layout_kernel<<<1, 1>>>((const unsigned*)edge_index);
    extract_zero_kernel<<<(E + 255) / 256, 256>>>(edge_index, E, M);
    histogram_kernel<<<(E + 255) / 256, 256>>>(E);
    int nb = (M + 1023) / 1024;
    scan1_kernel<<<nb, 1024>>>(M);
    scan2_kernel<<<1, 32>>>(nb);
    scan3_kernel<<<(M + 255) / 256, 256>>>(M, E);
    scatter_csr_kernel<<<(E + 255) / 256, 256>>>(E);

    // --- fold final layers ---
    fold_final_kernel<<<1, 128>>>(np_W, np_b, d_W3, d_b3, final_W, final_b);

    int gemm_grid = (M + BM - 1) / BM;

    // --- feat path ---
    tf32_gemm_kernel<<<gemm_grid, 256, GEMM_SMEM>>>(
        x, pre_W, FIN, nullptr, nullptr, 0, pre_b, hbuf, hb16, M, 0);
    mean_agg_kernel<<<(M * 32 + 255) / 256, 256>>>(hb16, aggbuf, M);
    tf32_gemm_kernel<<<gemm_grid, 256, GEMM_SMEM>>>(
        hbuf, c1_Ws, HD, aggbuf, c1_Wn, HD, c1_b, h2buf, hb16, M, 1);
    mean_agg_kernel<<<(M * 32 + 255) / 256, 256>>>(hb16, aggbuf, M);
    tf32_gemm_kernel<<<gemm_grid, 256, GEMM_SMEM>>>(
        h2buf, c2_Ws, HD, aggbuf, c2_Wn, HD, c2_b, hbuf, nullptr, M, 1);

    // --- dist path ---
    dist0_kernel<<<(M + D0_ROWS - 1) / D0_ROWS, 128>>>(edge_attr, d_W0, d_b0, y0buf, M);
    tf32_gemm_kernel<<<gemm_grid, 256, GEMM_SMEM>>>(
        y0buf, d_W1, HD, nullptr, nullptr, 0, d_b1, y1buf, nullptr, M, 1);
    tf32_gemm_kernel<<<gemm_grid, 256, GEMM_SMEM>>>(
        y1buf, d_W2, HD, nullptr, nullptr, 0, d_b2, y0buf, nullptr, M, 1);

    // --- fused final ---
    final_dot_kernel<<<(M * 32 + 255) / 256, 256>>>(hbuf, y0buf, out, M);
}

// round 7
// speedup vs baseline: 3.1453x; 1.2720x over previous
#include <cuda_runtime.h>
#include <cuda_bf16.h>
#include <math.h>

// ---------------- problem constants ----------------
#define NN  100000
#define HD  128
#define EE  1600000
#define FIN 256
#define KD  5

// ---------------- scratch (static __device__, no allocation) ----------------
__device__ float g_h  [(size_t)NN * HD];   // fp32 feat-final (c2 out)
__device__ float g_y0 [(size_t)NN * HD];   // fp32 dist-final (d2 out)
__device__ __nv_bfloat16 g_hb16 [(size_t)NN * HD];
__device__ __nv_bfloat16 g_h2b16[(size_t)NN * HD];
__device__ __nv_bfloat16 g_aggb16[(size_t)NN * HD];
__device__ __nv_bfloat16 g_y0b16[(size_t)NN * HD];
__device__ __nv_bfloat16 g_y1b16[(size_t)NN * HD];
__device__ __nv_bfloat16 g_wt[6 * HD * HD];   // transposed bf16 weights [n][k]

__device__ int g_src[EE];
__device__ int g_dstv[EE];
__device__ int g_csr_src[EE];
__device__ int g_counts[NN];
__device__ int g_incl[NN];
__device__ int g_offs[NN + 1];
__device__ int g_cursor[NN];
__device__ int g_bsum[256];
__device__ int g_flag64;

// folded final-layer vectors: out = sigmoid(h_final . vfeat + y2 . vdist + cc)
__device__ float g_vfeat[HD];
__device__ float g_vdist[HD];
__device__ float g_cc;

// ---------------- edge-index dtype detection ----------------
__global__ void detect_layout_kernel(const unsigned* __restrict__ p) {
    unsigned any = 0;
#pragma unroll
    for (int i = 1; i < 64; i += 2) any |= p[i];
    g_flag64 = (any == 0) ? 1 : 0;
}

// merged: zero counts (i < n) + extract edges (i < E)
__global__ void extract_zero_kernel(const void* __restrict__ edge_index, int E, int n) {
    int i = blockIdx.x * blockDim.x + threadIdx.x;
    if (i < n) g_counts[i] = 0;
    if (i >= E) return;
    if (g_flag64) {
        const long long* p = (const long long*)edge_index;
        g_src[i]  = (int)p[i];
        g_dstv[i] = (int)p[(size_t)E + i];
    } else {
        const int* p = (const int*)edge_index;
        g_src[i]  = p[i];
        g_dstv[i] = p[E + i];
    }
}

// ---------------- CSR build (counting sort by dst) ----------------
__global__ void histogram_kernel(int E) {
    int i = blockIdx.x * blockDim.x + threadIdx.x;
    if (i < E) atomicAdd(&g_counts[g_dstv[i]], 1);
}

__global__ void scan1_kernel(int n) {
    __shared__ int s[1024];
    int i = blockIdx.x * 1024 + threadIdx.x;
    int v = (i < n) ? g_counts[i] : 0;
    s[threadIdx.x] = v;
    __syncthreads();
#pragma unroll
    for (int off = 1; off < 1024; off <<= 1) {
        int t = (threadIdx.x >= off) ? s[threadIdx.x - off] : 0;
        __syncthreads();
        s[threadIdx.x] += t;
        __syncthreads();
    }
    if (i < n) g_incl[i] = s[threadIdx.x];
    if (threadIdx.x == 1023) g_bsum[blockIdx.x] = s[1023];
}

__global__ void scan2_kernel(int nb) {
    if (threadIdx.x == 0 && blockIdx.x == 0) {
        int run = 0;
        for (int i = 0; i < nb; ++i) {
            int v = g_bsum[i];
            g_bsum[i] = run;
            run += v;
        }
    }
}

__global__ void scan3_kernel(int n, int E) {
    int i = blockIdx.x * blockDim.x + threadIdx.x;
    if (i >= n) return;
    int off = g_bsum[i >> 10] + g_incl[i] - g_counts[i];
    g_offs[i] = off;
    g_cursor[i] = off;
    if (i == n - 1) g_offs[n] = E;
}

__global__ void scatter_csr_kernel(int E) {
    int i = blockIdx.x * blockDim.x + threadIdx.x;
    if (i >= E) return;
    int d = g_dstv[i];
    int p = atomicAdd(&g_cursor[d], 1);
    g_csr_src[p] = g_src[i];
}

// ---------------- weight transpose+convert: W[k][n] fp32 -> Wt[n][k] bf16 ----------------
// slots: 0=c1_Ws 1=c1_Wn 2=c2_Ws 3=c2_Wn 4=d_W1 5=d_W2
__global__ void wt_kernel(const float* __restrict__ w0, const float* __restrict__ w1,
                          const float* __restrict__ w2, const float* __restrict__ w3,
                          const float* __restrict__ w4, const float* __restrict__ w5)
{
    int i = blockIdx.x * 256 + threadIdx.x;     // 6*16384
    if (i >= 6 * HD * HD) return;
    int m = i >> 14;
    int r = i & (HD * HD - 1);
    int n = r >> 7;
    int k = r & 127;
    const float* src = (m == 0) ? w0 : (m == 1) ? w1 : (m == 2) ? w2
                     : (m == 3) ? w3 : (m == 4) ? w4 : w5;
    g_wt[i] = __float2bfloat16(src[k * HD + n]);
}

// ---------------- mean aggregation: bf16 gather -> bf16 out, one warp/node ----------------
__global__ void mean_agg_kernel(const __nv_bfloat16* __restrict__ h16,
                                __nv_bfloat16* __restrict__ agg16, int n) {
    int warp = (blockIdx.x * blockDim.x + threadIdx.x) >> 5;
    int lane = threadIdx.x & 31;
    if (warp >= n) return;
    int s = g_offs[warp];
    int e = g_offs[warp + 1];
    float a0 = 0.f, a1 = 0.f, a2 = 0.f, a3 = 0.f;
    int i = s;
    for (; i + 4 <= e; i += 4) {
        int s0 = __ldg(&g_csr_src[i]);
        int s1 = __ldg(&g_csr_src[i + 1]);
        int s2 = __ldg(&g_csr_src[i + 2]);
        int s3 = __ldg(&g_csr_src[i + 3]);
        uint2 u0 = ((const uint2*)(h16 + (size_t)s0 * HD))[lane];
        uint2 u1 = ((const uint2*)(h16 + (size_t)s1 * HD))[lane];
        uint2 u2 = ((const uint2*)(h16 + (size_t)s2 * HD))[lane];
        uint2 u3 = ((const uint2*)(h16 + (size_t)s3 * HD))[lane];
        float2 p;
        p = __bfloat1622float2(*(__nv_bfloat162*)&u0.x); a0 += p.x; a1 += p.y;
        p = __bfloat1622float2(*(__nv_bfloat162*)&u0.y); a2 += p.x; a3 += p.y;
        p = __bfloat1622float2(*(__nv_bfloat162*)&u1.x); a0 += p.x; a1 += p.y;
        p = __bfloat1622float2(*(__nv_bfloat162*)&u1.y); a2 += p.x; a3 += p.y;
        p = __bfloat1622float2(*(__nv_bfloat162*)&u2.x); a0 += p.x; a1 += p.y;
        p = __bfloat1622float2(*(__nv_bfloat162*)&u2.y); a2 += p.x; a3 += p.y;
        p = __bfloat1622float2(*(__nv_bfloat162*)&u3.x); a0 += p.x; a1 += p.y;
        p = __bfloat1622float2(*(__nv_bfloat162*)&u3.y); a2 += p.x; a3 += p.y;
    }
    for (; i < e; ++i) {
        int s0 = __ldg(&g_csr_src[i]);
        uint2 u0 = ((const uint2*)(h16 + (size_t)s0 * HD))[lane];
        float2 p;
        p = __bfloat1622float2(*(__nv_bfloat162*)&u0.x); a0 += p.x; a1 += p.y;
        p = __bfloat1622float2(*(__nv_bfloat162*)&u0.y); a2 += p.x; a3 += p.y;
    }
    float inv = 1.0f / (float)max(e - s, 1);
    uint2 r;
    *(__nv_bfloat162*)&r.x = __float22bfloat162_rn(make_float2(a0 * inv, a1 * inv));
    *(__nv_bfloat162*)&r.y = __float22bfloat162_rn(make_float2(a2 * inv, a3 * inv));
    ((uint2*)(agg16 + (size_t)warp * HD))[lane] = r;
}

// ================= common helpers =================
__device__ __forceinline__ unsigned smem_u32p(const void* p) {
    return (unsigned)__cvta_generic_to_shared(p);
}
__device__ __forceinline__ void cp_async16(unsigned dst, const void* src, int pred) {
    asm volatile("cp.async.cg.shared.global [%0], [%1], 16, %2;\n"
                 :: "r"(dst), "l"(src), "r"(pred ? 16 : 0));
}

// ---------------- TF32 GEMM (pre layer, K=256), cp.async 2-stage ----------------
#define BM 128
#define BN 128
#define BK 32
#define SA 36
#define SB 136
#define STAGE_FLOATS 8960
#define GEMM_SMEM   (2 * STAGE_FLOATS * 4)

__device__ __forceinline__ void gemm_load_tile(
    float* As, float* Bs, const float* __restrict__ A, const float* __restrict__ W,
    int K, int k0, int row0, int M, int tid)
{
#pragma unroll
    for (int i = 0; i < 4; ++i) {
        int c = tid + i * 256;
        int r = c >> 3;
        int off = (c & 7) * 4;
        int gr = row0 + r;
        cp_async16(smem_u32p(As + r * SA + off),
                   A + (size_t)gr * K + k0 + off, gr < M);
    }
#pragma unroll
    for (int i = 0; i < 4; ++i) {
        int c = tid + i * 256;
        int r = c >> 5;
        int off = (c & 31) * 4;
        cp_async16(smem_u32p(Bs + r * SB + off),
                   W + (size_t)(k0 + r) * BN + off, 1);
    }
    asm volatile("cp.async.commit_group;\n" ::);
}

__device__ __forceinline__ void mma_tf32(float* c, const unsigned* a, const unsigned* b) {
    asm volatile(
        "mma.sync.aligned.m16n8k8.row.col.f32.tf32.tf32.f32 "
        "{%0,%1,%2,%3}, {%4,%5,%6,%7}, {%8,%9}, {%0,%1,%2,%3};"
        : "+f"(c[0]), "+f"(c[1]), "+f"(c[2]), "+f"(c[3])
        : "r"(a[0]), "r"(a[1]), "r"(a[2]), "r"(a[3]), "r"(b[0]), "r"(b[1]));
}

__global__ void __launch_bounds__(256) tf32_gemm_kernel(
    const float* __restrict__ A1, const float* __restrict__ W1, int K1,
    const float* __restrict__ bias, float* __restrict__ C,
    __nv_bfloat16* __restrict__ C16, int M, int do_relu)
{
    extern __shared__ float sm[];
    float* AsB[2] = { sm,            sm + STAGE_FLOATS };
    float* BsB[2] = { sm + 128 * SA, sm + STAGE_FLOATS + 128 * SA };

    int tid = threadIdx.x;
    int lane = tid & 31;
    int warp = tid >> 5;
    int wm = (warp >> 2) * 64;
    int wn = (warp & 3) * 32;
    int row0 = blockIdx.x * BM;
    int g = lane >> 2;
    int q = lane & 3;

    float acc[4][4][4];
#pragma unroll
    for (int i = 0; i < 4; ++i)
#pragma unroll
        for (int j = 0; j < 4; ++j)
#pragma unroll
            for (int k = 0; k < 4; ++k) acc[i][j][k] = 0.f;

    int total = K1 >> 5;
    gemm_load_tile(AsB[0], BsB[0], A1, W1, K1, 0, row0, M, tid);

    for (int t = 0; t < total; ++t) {
        if (t + 1 < total) {
            gemm_load_tile(AsB[(t + 1) & 1], BsB[(t + 1) & 1], A1, W1, K1,
                           (t + 1) * BK, row0, M, tid);
            asm volatile("cp.async.wait_group 1;\n" ::);
        } else {
            asm volatile("cp.async.wait_group 0;\n" ::);
        }
        __syncthreads();

        const float* As = AsB[t & 1];
        const float* Bs = BsB[t & 1];
#pragma unroll
        for (int kk = 0; kk < BK; kk += 8) {
            int kq = kk + q;
            unsigned a[4][4], b[4][2];
#pragma unroll
            for (int fm = 0; fm < 4; ++fm) {
                int m = wm + fm * 16 + g;
                a[fm][0] = __float_as_uint(As[m * SA + kq]);
                a[fm][1] = __float_as_uint(As[(m + 8) * SA + kq]);
                a[fm][2] = __float_as_uint(As[m * SA + kq + 4]);
                a[fm][3] = __float_as_uint(As[(m + 8) * SA + kq + 4]);
            }
#pragma unroll
            for (int fn = 0; fn < 4; ++fn) {
                int n = wn + fn * 8 + g;
                b[fn][0] = __float_as_uint(Bs[kq * SB + n]);
                b[fn][1] = __float_as_uint(Bs[(kq + 4) * SB + n]);
            }
#pragma unroll
            for (int fm = 0; fm < 4; ++fm)
#pragma unroll
                for (int fn = 0; fn < 4; ++fn)
                    mma_tf32(acc[fm][fn], a[fm], b[fn]);
        }
        __syncthreads();
    }

#pragma unroll
    for (int fm = 0; fm < 4; ++fm) {
#pragma unroll
        for (int fn = 0; fn < 4; ++fn) {
            int r = row0 + wm + fm * 16 + g;
            int c = wn + fn * 8 + (q << 1);
            float b0 = bias[c], b1 = bias[c + 1];
            float v0 = acc[fm][fn][0] + b0;
            float v1 = acc[fm][fn][1] + b1;
            float v2 = acc[fm][fn][2] + b0;
            float v3 = acc[fm][fn][3] + b1;
            if (do_relu) {
                v0 = fmaxf(v0, 0.f); v1 = fmaxf(v1, 0.f);
                v2 = fmaxf(v2, 0.f); v3 = fmaxf(v3, 0.f);
            }
            if (r < M) {
                if (C)   *(float2*)(C + (size_t)r * BN + c) = make_float2(v0, v1);
                if (C16) *(__nv_bfloat162*)(C16 + (size_t)r * BN + c) =
                             __float22bfloat162_rn(make_float2(v0, v1));
            }
            if (r + 8 < M) {
                if (C)   *(float2*)(C + (size_t)(r + 8) * BN + c) = make_float2(v2, v3);
                if (C16) *(__nv_bfloat162*)(C16 + (size_t)(r + 8) * BN + c) =
                             __float22bfloat162_rn(make_float2(v2, v3));
            }
        }
    }
}

// ---------------- BF16 GEMM (K=128 per source), dual-problem batched ----------------
// Problem A: C = act(A1@Wt1^T + A2@Wt2^T + bias)   (A2 may be null)
// Problem B: C = act(A1@Wt1^T + bias)
// A row-major [M,128] bf16; Wt row-major [n][k] bf16 (pre-transposed).
#define SAH 40   // bf16 smem stride: fragment banks (20m+q)%32 all distinct

__device__ __forceinline__ void bf16_load_tile(
    __nv_bfloat16* As, __nv_bfloat16* Bs,
    const __nv_bfloat16* __restrict__ A, const __nv_bfloat16* __restrict__ Wt,
    int k0, int row0, int M, int tid)
{
#pragma unroll
    for (int i = 0; i < 2; ++i) {
        int c = tid + i * 256;
        int r = c >> 2;
        int j = c & 3;
        int gr = row0 + r;
        cp_async16(smem_u32p(As + r * SAH + j * 8),
                   A + (size_t)gr * HD + k0 + j * 8, gr < M);
    }
#pragma unroll
    for (int i = 0; i < 2; ++i) {
        int c = tid + i * 256;
        int r = c >> 2;
        int j = c & 3;
        cp_async16(smem_u32p(Bs + r * SAH + j * 8),
                   Wt + (size_t)r * HD + k0 + j * 8, 1);
    }
    asm volatile("cp.async.commit_group;\n" ::);
}

__device__ __forceinline__ void mma_bf16(float* c, const unsigned* a, const unsigned* b) {
    asm volatile(
        "mma.sync.aligned.m16n8k16.row.col.f32.bf16.bf16.f32 "
        "{%0,%1,%2,%3}, {%4,%5,%6,%7}, {%8,%9}, {%0,%1,%2,%3};"
        : "+f"(c[0]), "+f"(c[1]), "+f"(c[2]), "+f"(c[3])
        : "r"(a[0]), "r"(a[1]), "r"(a[2]), "r"(a[3]), "r"(b[0]), "r"(b[1]));
}

__global__ void __launch_bounds__(256, 2) bf16_gemm_dual(
    const __nv_bfloat16* __restrict__ A1a, const __nv_bfloat16* __restrict__ Wt1a,
    const __nv_bfloat16* __restrict__ A2a, const __nv_bfloat16* __restrict__ Wt2a,
    const float* __restrict__ biasa, float* __restrict__ Ca,
    __nv_bfloat16* __restrict__ C16a, int reluA,
    const __nv_bfloat16* __restrict__ A1b, const __nv_bfloat16* __restrict__ Wt1b,
    const float* __restrict__ biasb, float* __restrict__ Cb,
    __nv_bfloat16* __restrict__ C16b, int reluB,
    int M, int grid1)
{
    __shared__ __nv_bfloat16 smA[2][128 * SAH];
    __shared__ __nv_bfloat16 smB[2][128 * SAH];

    int tid = threadIdx.x;
    int lane = tid & 31;
    int warp = tid >> 5;
    int wm = (warp >> 2) * 64;
    int wn = (warp & 3) * 32;
    int g = lane >> 2;
    int q = lane & 3;

    int probB = (blockIdx.x >= grid1);
    int row0 = (probB ? (blockIdx.x - grid1) : blockIdx.x) * BM;

    const __nv_bfloat16* Asrc[2];
    const __nv_bfloat16* Wsrc[2];
    int nsrc;
    const float* bias;
    float* C;
    __nv_bfloat16* C16;
    int do_relu;
    if (probB) {
        Asrc[0] = A1b; Wsrc[0] = Wt1b; Asrc[1] = A1b; Wsrc[1] = Wt1b;
        nsrc = 1; bias = biasb; C = Cb; C16 = C16b; do_relu = reluB;
    } else {
        Asrc[0] = A1a; Wsrc[0] = Wt1a; Asrc[1] = A2a; Wsrc[1] = Wt2a;
        nsrc = A2a ? 2 : 1; bias = biasa; C = Ca; C16 = C16a; do_relu = reluA;
    }

    float acc[4][4][4];
#pragma unroll
    for (int i = 0; i < 4; ++i)
#pragma unroll
        for (int j = 0; j < 4; ++j)
#pragma unroll
            for (int k = 0; k < 4; ++k) acc[i][j][k] = 0.f;

    int total = nsrc * 4;          // K=128 per source, BK=32
    bf16_load_tile(smA[0], smB[0], Asrc[0], Wsrc[0], 0, row0, M, tid);

    for (int t = 0; t < total; ++t) {
        if (t + 1 < total) {
            int p = (t + 1) >> 2;
            int k0 = ((t + 1) & 3) * BK;
            bf16_load_tile(smA[(t + 1) & 1], smB[(t + 1) & 1],
                           Asrc[p], Wsrc[p], k0, row0, M, tid);
            asm volatile("cp.async.wait_group 1;\n" ::);
        } else {
            asm volatile("cp.async.wait_group 0;\n" ::);
        }
        __syncthreads();

        const __nv_bfloat16* As = smA[t & 1];
        const __nv_bfloat16* Bs = smB[t & 1];
#pragma unroll
        for (int kk = 0; kk < BK; kk += 16) {
            int kq = kk + 2 * q;
            unsigned a[4][4], b[4][2];
#pragma unroll
            for (int fm = 0; fm < 4; ++fm) {
                int m = wm + fm * 16 + g;
                a[fm][0] = *(const unsigned*)&As[m * SAH + kq];
                a[fm][1] = *(const unsigned*)&As[(m + 8) * SAH + kq];
                a[fm][2] = *(const unsigned*)&As[m * SAH + kq + 8];
                a[fm][3] = *(const unsigned*)&As[(m + 8) * SAH + kq + 8];
            }
#pragma unroll
            for (int fn = 0; fn < 4; ++fn) {
                int n = wn + fn * 8 + g;
                b[fn][0] = *(const unsigned*)&Bs[n * SAH + kq];
                b[fn][1] = *(const unsigned*)&Bs[n * SAH + kq + 8];
            }
#pragma unroll
            for (int fm = 0; fm < 4; ++fm)
#pragma unroll
                for (int fn = 0; fn < 4; ++fn)
                    mma_bf16(acc[fm][fn], a[fm], b[fn]);
        }
        __syncthreads();
    }

#pragma unroll
    for (int fm = 0; fm < 4; ++fm) {
#pragma unroll
        for (int fn = 0; fn < 4; ++fn) {
            int r = row0 + wm + fm * 16 + g;
            int c = wn + fn * 8 + (q << 1);
            float b0 = bias[c], b1 = bias[c + 1];
            float v0 = acc[fm][fn][0] + b0;
            float v1 = acc[fm][fn][1] + b1;
            float v2 = acc[fm][fn][2] + b0;
            float v3 = acc[fm][fn][3] + b1;
            if (do_relu) {
                v0 = fmaxf(v0, 0.f); v1 = fmaxf(v1, 0.f);
                v2 = fmaxf(v2, 0.f); v3 = fmaxf(v3, 0.f);
            }
            if (r < M) {
                if (C)   *(float2*)(C + (size_t)r * BN + c) = make_float2(v0, v1);
                if (C16) *(__nv_bfloat162*)(C16 + (size_t)r * BN + c) =
                             __float22bfloat162_rn(make_float2(v0, v1));
            }
            if (r + 8 < M) {
                if (C)   *(float2*)(C + (size_t)(r + 8) * BN + c) = make_float2(v2, v3);
                if (C16) *(__nv_bfloat162*)(C16 + (size_t)(r + 8) * BN + c) =
                             __float22bfloat162_rn(make_float2(v2, v3));
            }
        }
    }
}

// ---------------- dist layer0 : y = relu(e[M,5] @ W0[5,128] + b0) -> bf16 ----------------
#define D0_ROWS 16
__global__ void dist0_kernel(const float* __restrict__ e, const float* __restrict__ W0,
                             const float* __restrict__ b0,
                             __nv_bfloat16* __restrict__ y, int M)
{
    __shared__ float ws[KD * HD];
    for (int i = threadIdx.x; i < KD * HD; i += blockDim.x) ws[i] = W0[i];
    __syncthreads();
    int c = threadIdx.x;
    float bv = b0[c];
    int r0 = blockIdx.x * D0_ROWS;
    for (int rr = 0; rr < D0_ROWS; ++rr) {
        int r = r0 + rr;
        if (r >= M) return;
        float acc = bv;
#pragma unroll
        for (int k = 0; k < KD; ++k)
            acc += e[(size_t)r * KD + k] * ws[k * HD + c];
        y[(size_t)r * HD + c] = __float2bfloat16(fmaxf(acc, 0.f));
    }
}

// ---------------- fold nodepost + d3 + final_W into two 128-vectors ----------------
__global__ void fold_final_kernel(
    const float* __restrict__ np_W, const float* __restrict__ np_b,
    const float* __restrict__ d_W3, const float* __restrict__ d_b3,
    const float* __restrict__ fW, const float* __restrict__ fb)
{
    int j = threadIdx.x;  // 128
    float vf = 0.f, vd = 0.f;
#pragma unroll 8
    for (int k = 0; k < HD; ++k) {
        vf += np_W[j * HD + k] * fW[k];
        vd += d_W3[j * HD + k] * fW[HD + k];
    }
    g_vfeat[j] = vf;
    g_vdist[j] = vd;
    if (j == 0) {
        float c = fb[0];
        for (int k = 0; k < HD; ++k)
            c += np_b[k] * fW[k] + d_b3[k] * fW[HD + k];
        g_cc = c;
    }
}

// ---------------- fused final: out = sigmoid(h.vfeat + y2.vdist + cc) ----------------
__global__ void final_dot_kernel(const float* __restrict__ hfin, const float* __restrict__ y2,
                                 float* __restrict__ out, int M)
{
    __shared__ float w[2 * HD];
    if (threadIdx.x < HD)          w[threadIdx.x] = g_vfeat[threadIdx.x];
    else if (threadIdx.x < 2 * HD) w[threadIdx.x] = g_vdist[threadIdx.x - HD];
    __syncthreads();
    int warp = (blockIdx.x * blockDim.x + threadIdx.x) >> 5;
    int lane = threadIdx.x & 31;
    if (warp >= M) return;
    float4 f = ((const float4*)(hfin + (size_t)warp * HD))[lane];
    float4 d = ((const float4*)(y2 + (size_t)warp * HD))[lane];
    float4 wf = ((const float4*)w)[lane];
    float4 wd = ((const float4*)w)[lane + 32];
    float sum = f.x * wf.x + f.y * wf.y + f.z * wf.z + f.w * wf.w
              + d.x * wd.x + d.y * wd.y + d.z * wd.z + d.w * wd.w;
#pragma unroll
    for (int off = 16; off > 0; off >>= 1)
        sum += __shfl_xor_sync(0xFFFFFFFF, sum, off);
    if (lane == 0) {
        float v = sum + g_cc;
        out[warp] = 1.0f / (1.0f + __expf(-v));
    }
}

// ---------------- launch ----------------
extern "C" void kernel_launch(void* const* d_in, const int* in_sizes, int n_in,
                              void* d_out, int out_size)
{
    const float* x          = (const float*)d_in[0];
    const void*  edge_index = d_in[1];
    const float* edge_attr  = (const float*)d_in[2];
    const float* pre_W      = (const float*)d_in[3];
    const float* pre_b      = (const float*)d_in[4];
    const float* c1_Ws      = (const float*)d_in[5];
    const float* c1_Wn      = (const float*)d_in[6];
    const float* c1_b       = (const float*)d_in[7];
    const float* c2_Ws      = (const float*)d_in[8];
    const float* c2_Wn      = (const float*)d_in[9];
    const float* c2_b       = (const float*)d_in[10];
    const float* np_W       = (const float*)d_in[11];
    const float* np_b       = (const float*)d_in[12];
    const float* d_W0       = (const float*)d_in[13];
    const float* d_b0       = (const float*)d_in[14];
    const float* d_W1       = (const float*)d_in[15];
    const float* d_b1       = (const float*)d_in[16];
    const float* d_W2       = (const float*)d_in[17];
    const float* d_b2       = (const float*)d_in[18];
    const float* d_W3       = (const float*)d_in[19];
    const float* d_b3       = (const float*)d_in[20];
    const float* final_W    = (const float*)d_in[21];
    const float* final_b    = (const float*)d_in[22];
    float* out = (float*)d_out;

    int M = NN;
    int E = in_sizes[1] / 2;
    if (E > EE) E = EE;

    float *hbuf, *y0buf;
    __nv_bfloat16 *hb16, *h2b16, *aggb16, *y0b16, *y1b16, *wt;
    cudaGetSymbolAddress((void**)&hbuf,   g_h);
    cudaGetSymbolAddress((void**)&y0buf,  g_y0);
    cudaGetSymbolAddress((void**)&hb16,   g_hb16);
    cudaGetSymbolAddress((void**)&h2b16,  g_h2b16);
    cudaGetSymbolAddress((void**)&aggb16, g_aggb16);
    cudaGetSymbolAddress((void**)&y0b16,  g_y0b16);
    cudaGetSymbolAddress((void**)&y1b16,  g_y1b16);
    cudaGetSymbolAddress((void**)&wt,     g_wt);

    cudaFuncSetAttribute(tf32_gemm_kernel,
                         cudaFuncAttributeMaxDynamicSharedMemorySize, GEMM_SMEM);

    // --- CSR build ---
    detect_layout_kernel<<<1, 1>>>((const unsigned*)edge_index);
    extract_zero_kernel<<<(E + 255) / 256, 256>>>(edge_index, E, M);
    histogram_kernel<<<(E + 255) / 256, 256>>>(E);
    int nb = (M + 1023) / 1024;
    scan1_kernel<<<nb, 1024>>>(M);
    scan2_kernel<<<1, 32>>>(nb);
    scan3_kernel<<<(M + 255) / 256, 256>>>(M, E);
    scatter_csr_kernel<<<(E + 255) / 256, 256>>>(E);

    // --- constant prep ---
    fold_final_kernel<<<1, 128>>>(np_W, np_b, d_W3, d_b3, final_W, final_b);
    wt_kernel<<<(6 * HD * HD + 255) / 256, 256>>>(c1_Ws, c1_Wn, c2_Ws, c2_Wn, d_W1, d_W2);

    const __nv_bfloat16* wt_c1s = wt + 0 * HD * HD;
    const __nv_bfloat16* wt_c1n = wt + 1 * HD * HD;
    const __nv_bfloat16* wt_c2s = wt + 2 * HD * HD;
    const __nv_bfloat16* wt_c2n = wt + 3 * HD * HD;
    const __nv_bfloat16* wt_d1  = wt + 4 * HD * HD;
    const __nv_bfloat16* wt_d2  = wt + 5 * HD * HD;

    int G = (M + BM - 1) / BM;

    // --- pre layer (tf32, K=256) + dist0 ---
    tf32_gemm_kernel<<<G, 256, GEMM_SMEM>>>(x, pre_W, FIN, pre_b, nullptr, hb16, M, 0);
    dist0_kernel<<<(M + D0_ROWS - 1) / D0_ROWS, 128>>>(edge_attr, d_W0, d_b0, y0b16, M);

    // --- agg1 ---
    mean_agg_kernel<<<(M * 32 + 255) / 256, 256>>>(hb16, aggb16, M);

    // --- layer1 conv (c1) + dist layer1 (d1), batched ---
    bf16_gemm_dual<<<2 * G, 256>>>(
        hb16, wt_c1s, aggb16, wt_c1n, c1_b, nullptr, h2b16, 1,
        y0b16, wt_d1, d_b1, nullptr, y1b16, 1,
        M, G);

    // --- agg2 ---
    mean_agg_kernel<<<(M * 32 + 255) / 256, 256>>>(h2b16, aggb16, M);

    // --- layer2 conv (c2) + dist layer2 (d2), batched; fp32 outs for final ---
    bf16_gemm_dual<<<2 * G, 256>>>(
        h2b16, wt_c2s, aggb16, wt_c2n, c2_b, hbuf, nullptr, 1,
        y1b16, wt_d2, d_b2, y0buf, nullptr, 1,
        M, G);

    // --- fused final ---
    final_dot_kernel<<<(M * 32 + 255) / 256, 256>>>(hbuf, y0buf, out, M);
}

// round 8
// speedup vs baseline: 3.2808x; 1.0431x over previous
#include <cuda_runtime.h>
#include <cuda_bf16.h>
#include <math.h>

// ---------------- problem constants ----------------
#define NN  100000
#define HD  128
#define EE  1600000
#define FIN 256
#define KD  5

// ---------------- scratch (static __device__, no allocation) ----------------
__device__ __nv_bfloat16 g_hb16 [(size_t)NN * HD];
__device__ __nv_bfloat16 g_h2b16[(size_t)NN * HD];
__device__ __nv_bfloat16 g_aggb16[(size_t)NN * HD];
__device__ __nv_bfloat16 g_y0b16[(size_t)NN * HD];
__device__ __nv_bfloat16 g_y1b16[(size_t)NN * HD];
__device__ __nv_bfloat16 g_wt[6 * HD * HD];   // transposed bf16 weights [n][k]

__device__ int g_csr_src[EE];
__device__ int g_counts[NN];
__device__ int g_incl[NN];
__device__ int g_offs[NN + 1];
__device__ int g_cursor[NN];
__device__ int g_bsum[256];
__device__ int g_flag64;

// folded final-layer vectors: out = sigmoid(h_final . vfeat + y2 . vdist + cc)
__device__ float g_vfeat[HD];
__device__ float g_vdist[HD];
__device__ float g_cc;

// ---------------- edge-index dtype detection ----------------
__global__ void detect_layout_kernel(const unsigned* __restrict__ p) {
    unsigned any = 0;
#pragma unroll
    for (int i = 1; i < 64; i += 2) any |= p[i];
    g_flag64 = (any == 0) ? 1 : 0;
}

// zero counts + zero out accumulator
__global__ void zero_kernel(float* __restrict__ out, int n) {
    int i = blockIdx.x * blockDim.x + threadIdx.x;
    if (i < n) { g_counts[i] = 0; out[i] = 0.f; }
}

// histogram straight from edge_index (dst half)
__global__ void histogram_kernel(const void* __restrict__ edge_index, int E) {
    int i = blockIdx.x * blockDim.x + threadIdx.x;
    if (i >= E) return;
    int d;
    if (g_flag64) d = (int)((const long long*)edge_index)[(size_t)E + i];
    else          d = ((const int*)edge_index)[E + i];
    atomicAdd(&g_counts[d], 1);
}

__global__ void scan1_kernel(int n) {
    __shared__ int s[1024];
    int i = blockIdx.x * 1024 + threadIdx.x;
    int v = (i < n) ? g_counts[i] : 0;
    s[threadIdx.x] = v;
    __syncthreads();
#pragma unroll
    for (int off = 1; off < 1024; off <<= 1) {
        int t = (threadIdx.x >= off) ? s[threadIdx.x - off] : 0;
        __syncthreads();
        s[threadIdx.x] += t;
        __syncthreads();
    }
    if (i < n) g_incl[i] = s[threadIdx.x];
    if (threadIdx.x == 1023) g_bsum[blockIdx.x] = s[1023];
}

__global__ void scan2_kernel(int nb) {
    if (threadIdx.x == 0 && blockIdx.x == 0) {
        int run = 0;
        for (int i = 0; i < nb; ++i) {
            int v = g_bsum[i];
            g_bsum[i] = run;
            run += v;
        }
    }
}

__global__ void scan3_kernel(int n, int E) {
    int i = blockIdx.x * blockDim.x + threadIdx.x;
    if (i >= n) return;
    int off = g_bsum[i >> 10] + g_incl[i] - g_counts[i];
    g_offs[i] = off;
    g_cursor[i] = off;
    if (i == n - 1) g_offs[n] = E;
}

// scatter straight from edge_index
__global__ void scatter_csr_kernel(const void* __restrict__ edge_index, int E) {
    int i = blockIdx.x * blockDim.x + threadIdx.x;
    if (i >= E) return;
    int s, d;
    if (g_flag64) {
        const long long* p = (const long long*)edge_index;
        s = (int)p[i];
        d = (int)p[(size_t)E + i];
    } else {
        const int* p = (const int*)edge_index;
        s = p[i];
        d = p[E + i];
    }
    int pos = atomicAdd(&g_cursor[d], 1);
    g_csr_src[pos] = s;
}

// ---------------- weight transpose+convert: W[k][n] fp32 -> Wt[n][k] bf16 ----------------
__global__ void wt_kernel(const float* __restrict__ w0, const float* __restrict__ w1,
                          const float* __restrict__ w2, const float* __restrict__ w3,
                          const float* __restrict__ w4, const float* __restrict__ w5)
{
    int i = blockIdx.x * 256 + threadIdx.x;     // 6*16384
    if (i >= 6 * HD * HD) return;
    int m = i >> 14;
    int r = i & (HD * HD - 1);
    int n = r >> 7;
    int k = r & 127;
    const float* src = (m == 0) ? w0 : (m == 1) ? w1 : (m == 2) ? w2
                     : (m == 3) ? w3 : (m == 4) ? w4 : w5;
    g_wt[i] = __float2bfloat16(src[k * HD + n]);
}

// ---------------- mean aggregation: 16 lanes/node, uint4 bf16 gather ----------------
__global__ void mean_agg_kernel(const __nv_bfloat16* __restrict__ h16,
                                __nv_bfloat16* __restrict__ agg16, int n) {
    int idx = blockIdx.x * blockDim.x + threadIdx.x;
    int node = idx >> 4;
    int lane = idx & 15;
    if (node >= n) return;
    int s = g_offs[node];
    int e = g_offs[node + 1];
    float a0 = 0.f, a1 = 0.f, a2 = 0.f, a3 = 0.f,
          a4 = 0.f, a5 = 0.f, a6 = 0.f, a7 = 0.f;
    int i = s;
    for (; i + 4 <= e; i += 4) {
        int s0 = __ldg(&g_csr_src[i]);
        int s1 = __ldg(&g_csr_src[i + 1]);
        int s2 = __ldg(&g_csr_src[i + 2]);
        int s3 = __ldg(&g_csr_src[i + 3]);
        uint4 u0 = ((const uint4*)(h16 + (size_t)s0 * HD))[lane];
        uint4 u1 = ((const uint4*)(h16 + (size_t)s1 * HD))[lane];
        uint4 u2 = ((const uint4*)(h16 + (size_t)s2 * HD))[lane];
        uint4 u3 = ((const uint4*)(h16 + (size_t)s3 * HD))[lane];
        float2 p;
#define ACC8(u) \
        p = __bfloat1622float2(*(__nv_bfloat162*)&(u).x); a0 += p.x; a1 += p.y; \
        p = __bfloat1622float2(*(__nv_bfloat162*)&(u).y); a2 += p.x; a3 += p.y; \
        p = __bfloat1622float2(*(__nv_bfloat162*)&(u).z); a4 += p.x; a5 += p.y; \
        p = __bfloat1622float2(*(__nv_bfloat162*)&(u).w); a6 += p.x; a7 += p.y;
        ACC8(u0); ACC8(u1); ACC8(u2); ACC8(u3);
    }
    for (; i < e; ++i) {
        int s0 = __ldg(&g_csr_src[i]);
        uint4 u0 = ((const uint4*)(h16 + (size_t)s0 * HD))[lane];
        float2 p;
        ACC8(u0);
    }
#undef ACC8
    float inv = 1.0f / (float)max(e - s, 1);
    uint4 r;
    *(__nv_bfloat162*)&r.x = __float22bfloat162_rn(make_float2(a0 * inv, a1 * inv));
    *(__nv_bfloat162*)&r.y = __float22bfloat162_rn(make_float2(a2 * inv, a3 * inv));
    *(__nv_bfloat162*)&r.z = __float22bfloat162_rn(make_float2(a4 * inv, a5 * inv));
    *(__nv_bfloat162*)&r.w = __float22bfloat162_rn(make_float2(a6 * inv, a7 * inv));
    ((uint4*)(agg16 + (size_t)node * HD))[lane] = r;
}

// ================= common helpers =================
__device__ __forceinline__ unsigned smem_u32p(const void* p) {
    return (unsigned)__cvta_generic_to_shared(p);
}
__device__ __forceinline__ void cp_async16(unsigned dst, const void* src, int pred) {
    asm volatile("cp.async.cg.shared.global [%0], [%1], 16, %2;\n"
                 :: "r"(dst), "l"(src), "r"(pred ? 16 : 0));
}

// ---------------- TF32 GEMM (pre layer, K=256), cp.async 2-stage ----------------
#define BM 128
#define BN 128
#define BK 32
#define SA 36
#define SB 136
#define STAGE_FLOATS 8960
#define GEMM_SMEM   (2 * STAGE_FLOATS * 4)

__device__ __forceinline__ void gemm_load_tile(
    float* As, float* Bs, const float* __restrict__ A, const float* __restrict__ W,
    int K, int k0, int row0, int M, int tid)
{
#pragma unroll
    for (int i = 0; i < 4; ++i) {
        int c = tid + i * 256;
        int r = c >> 3;
        int off = (c & 7) * 4;
        int gr = row0 + r;
        cp_async16(smem_u32p(As + r * SA + off),
                   A + (size_t)gr * K + k0 + off, gr < M);
    }
#pragma unroll
    for (int i = 0; i < 4; ++i) {
        int c = tid + i * 256;
        int r = c >> 5;
        int off = (c & 31) * 4;
        cp_async16(smem_u32p(Bs + r * SB + off),
                   W + (size_t)(k0 + r) * BN + off, 1);
    }
    asm volatile("cp.async.commit_group;\n" ::);
}

__device__ __forceinline__ void mma_tf32(float* c, const unsigned* a, const unsigned* b) {
    asm volatile(
        "mma.sync.aligned.m16n8k8.row.col.f32.tf32.tf32.f32 "
        "{%0,%1,%2,%3}, {%4,%5,%6,%7}, {%8,%9}, {%0,%1,%2,%3};"
        : "+f"(c[0]), "+f"(c[1]), "+f"(c[2]), "+f"(c[3])
        : "r"(a[0]), "r"(a[1]), "r"(a[2]), "r"(a[3]), "r"(b[0]), "r"(b[1]));
}

__global__ void __launch_bounds__(256) tf32_gemm_kernel(
    const float* __restrict__ A1, const float* __restrict__ W1, int K1,
    const float* __restrict__ bias, __nv_bfloat16* __restrict__ C16, int M)
{
    extern __shared__ float sm[];
    float* AsB[2] = { sm,            sm + STAGE_FLOATS };
    float* BsB[2] = { sm + 128 * SA, sm + STAGE_FLOATS + 128 * SA };

    int tid = threadIdx.x;
    int lane = tid & 31;
    int warp = tid >> 5;
    int wm = (warp >> 2) * 64;
    int wn = (warp & 3) * 32;
    int row0 = blockIdx.x * BM;
    int g = lane >> 2;
    int q = lane & 3;

    float acc[4][4][4];
#pragma unroll
    for (int i = 0; i < 4; ++i)
#pragma unroll
        for (int j = 0; j < 4; ++j)
#pragma unroll
            for (int k = 0; k < 4; ++k) acc[i][j][k] = 0.f;

    int total = K1 >> 5;
    gemm_load_tile(AsB[0], BsB[0], A1, W1, K1, 0, row0, M, tid);

    for (int t = 0; t < total; ++t) {
        if (t + 1 < total) {
            gemm_load_tile(AsB[(t + 1) & 1], BsB[(t + 1) & 1], A1, W1, K1,
                           (t + 1) * BK, row0, M, tid);
            asm volatile("cp.async.wait_group 1;\n" ::);
        } else {
            asm volatile("cp.async.wait_group 0;\n" ::);
        }
        __syncthreads();

        const float* As = AsB[t & 1];
        const float* Bs = BsB[t & 1];
#pragma unroll
        for (int kk = 0; kk < BK; kk += 8) {
            int kq = kk + q;
            unsigned a[4][4], b[4][2];
#pragma unroll
            for (int fm = 0; fm < 4; ++fm) {
                int m = wm + fm * 16 + g;
                a[fm][0] = __float_as_uint(As[m * SA + kq]);
                a[fm][1] = __float_as_uint(As[(m + 8) * SA + kq]);
                a[fm][2] = __float_as_uint(As[m * SA + kq + 4]);
                a[fm][3] = __float_as_uint(As[(m + 8) * SA + kq + 4]);
            }
#pragma unroll
            for (int fn = 0; fn < 4; ++fn) {
                int n = wn + fn * 8 + g;
                b[fn][0] = __float_as_uint(Bs[kq * SB + n]);
                b[fn][1] = __float_as_uint(Bs[(kq + 4) * SB + n]);
            }
#pragma unroll
            for (int fm = 0; fm < 4; ++fm)
#pragma unroll
                for (int fn = 0; fn < 4; ++fn)
                    mma_tf32(acc[fm][fn], a[fm], b[fn]);
        }
        __syncthreads();
    }

#pragma unroll
    for (int fm = 0; fm < 4; ++fm) {
#pragma unroll
        for (int fn = 0; fn < 4; ++fn) {
            int r = row0 + wm + fm * 16 + g;
            int c = wn + fn * 8 + (q << 1);
            float b0 = bias[c], b1 = bias[c + 1];
            float v0 = acc[fm][fn][0] + b0;
            float v1 = acc[fm][fn][1] + b1;
            float v2 = acc[fm][fn][2] + b0;
            float v3 = acc[fm][fn][3] + b1;
            if (r < M)
                *(__nv_bfloat162*)(C16 + (size_t)r * BN + c) =
                    __float22bfloat162_rn(make_float2(v0, v1));
            if (r + 8 < M)
                *(__nv_bfloat162*)(C16 + (size_t)(r + 8) * BN + c) =
                    __float22bfloat162_rn(make_float2(v2, v3));
        }
    }
}

// ---------------- BF16 GEMM (K=128 per source), dual-problem batched ----------------
// fold: 0=store bf16 C16, 1=dot with g_vfeat into out, 2=dot with g_vdist into out
#define SAH 40

__device__ __forceinline__ void bf16_load_tile(
    __nv_bfloat16* As, __nv_bfloat16* Bs,
    const __nv_bfloat16* __restrict__ A, const __nv_bfloat16* __restrict__ Wt,
    int k0, int row0, int M, int tid)
{
#pragma unroll
    for (int i = 0; i < 2; ++i) {
        int c = tid + i * 256;
        int r = c >> 2;
        int j = c & 3;
        int gr = row0 + r;
        cp_async16(smem_u32p(As + r * SAH + j * 8),
                   A + (size_t)gr * HD + k0 + j * 8, gr < M);
    }
#pragma unroll
    for (int i = 0; i < 2; ++i) {
        int c = tid + i * 256;
        int r = c >> 2;
        int j = c & 3;
        cp_async16(smem_u32p(Bs + r * SAH + j * 8),
                   Wt + (size_t)r * HD + k0 + j * 8, 1);
    }
    asm volatile("cp.async.commit_group;\n" ::);
}

__device__ __forceinline__ void mma_bf16(float* c, const unsigned* a, const unsigned* b) {
    asm volatile(
        "mma.sync.aligned.m16n8k16.row.col.f32.bf16.bf16.f32 "
        "{%0,%1,%2,%3}, {%4,%5,%6,%7}, {%8,%9}, {%0,%1,%2,%3};"
        : "+f"(c[0]), "+f"(c[1]), "+f"(c[2]), "+f"(c[3])
        : "r"(a[0]), "r"(a[1]), "r"(a[2]), "r"(a[3]), "r"(b[0]), "r"(b[1]));
}

__global__ void __launch_bounds__(256, 2) bf16_gemm_dual(
    const __nv_bfloat16* __restrict__ A1a, const __nv_bfloat16* __restrict__ Wt1a,
    const __nv_bfloat16* __restrict__ A2a, const __nv_bfloat16* __restrict__ Wt2a,
    const float* __restrict__ biasa, __nv_bfloat16* __restrict__ C16a, int foldA,
    const __nv_bfloat16* __restrict__ A1b, const __nv_bfloat16* __restrict__ Wt1b,
    const float* __restrict__ biasb, __nv_bfloat16* __restrict__ C16b, int foldB,
    float* __restrict__ out, int M, int grid1)
{
    __shared__ __nv_bfloat16 smA[2][128 * SAH];
    __shared__ __nv_bfloat16 smB[2][128 * SAH];
    __shared__ float sfv[BM];
    __shared__ float sred[BM];

    int tid = threadIdx.x;
    int lane = tid & 31;
    int warp = tid >> 5;
    int wm = (warp >> 2) * 64;
    int wn = (warp & 3) * 32;
    int g = lane >> 2;
    int q = lane & 3;

    int probB = (blockIdx.x >= grid1);
    int row0 = (probB ? (blockIdx.x - grid1) : blockIdx.x) * BM;

    const __nv_bfloat16* Asrc[2];
    const __nv_bfloat16* Wsrc[2];
    int nsrc;
    const float* bias;
    __nv_bfloat16* C16;
    int fold;
    if (probB) {
        Asrc[0] = A1b; Wsrc[0] = Wt1b; Asrc[1] = A1b; Wsrc[1] = Wt1b;
        nsrc = 1; bias = biasb; C16 = C16b; fold = foldB;
    } else {
        Asrc[0] = A1a; Wsrc[0] = Wt1a; Asrc[1] = A2a; Wsrc[1] = Wt2a;
        nsrc = A2a ? 2 : 1; bias = biasa; C16 = C16a; fold = foldA;
    }

    if (fold && tid < BM) {
        sfv[tid] = (fold == 1) ? g_vfeat[tid] : g_vdist[tid];
        sred[tid] = 0.f;
    }

    float acc[4][4][4];
#pragma unroll
    for (int i = 0; i < 4; ++i)
#pragma unroll
        for (int j = 0; j < 4; ++j)
#pragma unroll
            for (int k = 0; k < 4; ++k) acc[i][j][k] = 0.f;

    int total = nsrc * 4;
    bf16_load_tile(smA[0], smB[0], Asrc[0], Wsrc[0], 0, row0, M, tid);

    for (int t = 0; t < total; ++t) {
        if (t + 1 < total) {
            int p = (t + 1) >> 2;
            int k0 = ((t + 1) & 3) * BK;
            bf16_load_tile(smA[(t + 1) & 1], smB[(t + 1) & 1],
                           Asrc[p], Wsrc[p], k0, row0, M, tid);
            asm volatile("cp.async.wait_group 1;\n" ::);
        } else {
            asm volatile("cp.async.wait_group 0;\n" ::);
        }
        __syncthreads();

        const __nv_bfloat16* As = smA[t & 1];
        const __nv_bfloat16* Bs = smB[t & 1];
#pragma unroll
        for (int kk = 0; kk < BK; kk += 16) {
            int kq = kk + 2 * q;
            unsigned a[4][4], b[4][2];
#pragma unroll
            for (int fm = 0; fm < 4; ++fm) {
                int m = wm + fm * 16 + g;
                a[fm][0] = *(const unsigned*)&As[m * SAH + kq];
                a[fm][1] = *(const unsigned*)&As[(m + 8) * SAH + kq];
                a[fm][2] = *(const unsigned*)&As[m * SAH + kq + 8];
                a[fm][3] = *(const unsigned*)&As[(m + 8) * SAH + kq + 8];
            }
#pragma unroll
            for (int fn = 0; fn < 4; ++fn) {
                int n = wn + fn * 8 + g;
                b[fn][0] = *(const unsigned*)&Bs[n * SAH + kq];
                b[fn][1] = *(const unsigned*)&Bs[n * SAH + kq + 8];
            }
#pragma unroll
            for (int fm = 0; fm < 4; ++fm)
#pragma unroll
                for (int fn = 0; fn < 4; ++fn)
                    mma_bf16(acc[fm][fn], a[fm], b[fn]);
        }
        __syncthreads();
    }

    if (fold) {
        // relu(v) then dot with folded vector; reduce per row and add to out
#pragma unroll
        for (int fm = 0; fm < 4; ++fm) {
            float p0 = 0.f, p8 = 0.f;
#pragma unroll
            for (int fn = 0; fn < 4; ++fn) {
                int c = wn + fn * 8 + (q << 1);
                float b0 = bias[c], b1 = bias[c + 1];
                float w0 = sfv[c], w1 = sfv[c + 1];
                p0 += fmaxf(acc[fm][fn][0] + b0, 0.f) * w0
                    + fmaxf(acc[fm][fn][1] + b1, 0.f) * w1;
                p8 += fmaxf(acc[fm][fn][2] + b0, 0.f) * w0
                    + fmaxf(acc[fm][fn][3] + b1, 0.f) * w1;
            }
            atomicAdd(&sred[wm + fm * 16 + g], p0);
            atomicAdd(&sred[wm + fm * 16 + g + 8], p8);
        }
        __syncthreads();
        if (tid < BM) {
            int r = row0 + tid;
            if (r < M) atomicAdd(out + r, sred[tid]);
        }
    } else {
#pragma unroll
        for (int fm = 0; fm < 4; ++fm) {
#pragma unroll
            for (int fn = 0; fn < 4; ++fn) {
                int r = row0 + wm + fm * 16 + g;
                int c = wn + fn * 8 + (q << 1);
                float b0 = bias[c], b1 = bias[c + 1];
                float v0 = fmaxf(acc[fm][fn][0] + b0, 0.f);
                float v1 = fmaxf(acc[fm][fn][1] + b1, 0.f);
                float v2 = fmaxf(acc[fm][fn][2] + b0, 0.f);
                float v3 = fmaxf(acc[fm][fn][3] + b1, 0.f);
                if (r < M)
                    *(__nv_bfloat162*)(C16 + (size_t)r * BN + c) =
                        __float22bfloat162_rn(make_float2(v0, v1));
                if (r + 8 < M)
                    *(__nv_bfloat162*)(C16 + (size_t)(r + 8) * BN + c) =
                        __float22bfloat162_rn(make_float2(v2, v3));
            }
        }
    }
}

// ---------------- dist layer0 : y = relu(e[M,5] @ W0[5,128] + b0) -> bf16 ----------------
#define D0_ROWS 16
__global__ void dist0_kernel(const float* __restrict__ e, const float* __restrict__ W0,
                             const float* __restrict__ b0,
                             __nv_bfloat16* __restrict__ y, int M)
{
    __shared__ float ws[KD * HD];
    for (int i = threadIdx.x; i < KD * HD; i += blockDim.x) ws[i] = W0[i];
    __syncthreads();
    int c = threadIdx.x;
    float bv = b0[c];
    int r0 = blockIdx.x * D0_ROWS;
    for (int rr = 0; rr < D0_ROWS; ++rr) {
        int r = r0 + rr;
        if (r >= M) return;
        float acc = bv;
#pragma unroll
        for (int k = 0; k < KD; ++k)
            acc += e[(size_t)r * KD + k] * ws[k * HD + c];
        y[(size_t)r * HD + c] = __float2bfloat16(fmaxf(acc, 0.f));
    }
}

// ---------------- fold nodepost + d3 + final_W into two 128-vectors ----------------
__global__ void fold_final_kernel(
    const float* __restrict__ np_W, const float* __restrict__ np_b,
    const float* __restrict__ d_W3, const float* __restrict__ d_b3,
    const float* __restrict__ fW, const float* __restrict__ fb)
{
    int j = threadIdx.x;  // 128
    float vf = 0.f, vd = 0.f;
#pragma unroll 8
    for (int k = 0; k < HD; ++k) {
        vf += np_W[j * HD + k] * fW[k];
        vd += d_W3[j * HD + k] * fW[HD + k];
    }
    g_vfeat[j] = vf;
    g_vdist[j] = vd;
    if (j == 0) {
        float c = fb[0];
        for (int k = 0; k < HD; ++k)
            c += np_b[k] * fW[k] + d_b3[k] * fW[HD + k];
        g_cc = c;
    }
}

// ---------------- sigmoid epilogue ----------------
__global__ void sigmoid_kernel(float* __restrict__ out, int M) {
    int i = blockIdx.x * blockDim.x + threadIdx.x;
    if (i >= M) return;
    float v = out[i] + g_cc;
    out[i] = 1.0f / (1.0f + __expf(-v));
}

// ---------------- launch ----------------
extern "C" void kernel_launch(void* const* d_in, const int* in_sizes, int n_in,
                              void* d_out, int out_size)
{
    const float* x          = (const float*)d_in[0];
    const void*  edge_index = d_in[1];
    const float* edge_attr  = (const float*)d_in[2];
    const float* pre_W      = (const float*)d_in[3];
    const float* pre_b      = (const float*)d_in[4];
    const float* c1_Ws      = (const float*)d_in[5];
    const float* c1_Wn      = (const float*)d_in[6];
    const float* c1_b       = (const float*)d_in[7];
    const float* c2_Ws      = (const float*)d_in[8];
    const float* c2_Wn      = (const float*)d_in[9];
    const float* c2_b       = (const float*)d_in[10];
    const float* np_W       = (const float*)d_in[11];
    const float* np_b       = (const float*)d_in[12];
    const float* d_W0       = (const float*)d_in[13];
    const float* d_b0       = (const float*)d_in[14];
    const float* d_W1       = (const float*)d_in[15];
    const float* d_b1       = (const float*)d_in[16];
    const float* d_W2       = (const float*)d_in[17];
    const float* d_b2       = (const float*)d_in[18];
    const float* d_W3       = (const float*)d_in[19];
    const float* d_b3       = (const float*)d_in[20];
    const float* final_W    = (const float*)d_in[21];
    const float* final_b    = (const float*)d_in[22];
    float* out = (float*)d_out;

    int M = NN;
    int E = in_sizes[1] / 2;
    if (E > EE) E = EE;

    __nv_bfloat16 *hb16, *h2b16, *aggb16, *y0b16, *y1b16, *wt;
    cudaGetSymbolAddress((void**)&hb16,   g_hb16);
    cudaGetSymbolAddress((void**)&h2b16,  g_h2b16);
    cudaGetSymbolAddress((void**)&aggb16, g_aggb16);
    cudaGetSymbolAddress((void**)&y0b16,  g_y0b16);
    cudaGetSymbolAddress((void**)&y1b16,  g_y1b16);
    cudaGetSymbolAddress((void**)&wt,     g_wt);

    cudaFuncSetAttribute(tf32_gemm_kernel,
                         cudaFuncAttributeMaxDynamicSharedMemorySize, GEMM_SMEM);

    // --- CSR build (direct from edge_index) ---
    detect_layout_kernel<<<1, 1>>>((const unsigned*)edge_index);
    zero_kernel<<<(M + 255) / 256, 256>>>(out, M);
    histogram_kernel<<<(E + 255) / 256, 256>>>(edge_index, E);
    int nb = (M + 1023) / 1024;
    scan1_kernel<<<nb, 1024>>>(M);
    scan2_kernel<<<1, 32>>>(nb);
    scan3_kernel<<<(M + 255) / 256, 256>>>(M, E);
    scatter_csr_kernel<<<(E + 255) / 256, 256>>>(edge_index, E);

    // --- constant prep ---
    fold_final_kernel<<<1, 128>>>(np_W, np_b, d_W3, d_b3, final_W, final_b);
    wt_kernel<<<(6 * HD * HD + 255) / 256, 256>>>(c1_Ws, c1_Wn, c2_Ws, c2_Wn, d_W1, d_W2);

    const __nv_bfloat16* wt_c1s = wt + 0 * HD * HD;
    const __nv_bfloat16* wt_c1n = wt + 1 * HD * HD;
    const __nv_bfloat16* wt_c2s = wt + 2 * HD * HD;
    const __nv_bfloat16* wt_c2n = wt + 3 * HD * HD;
    const __nv_bfloat16* wt_d1  = wt + 4 * HD * HD;
    const __nv_bfloat16* wt_d2  = wt + 5 * HD * HD;

    int G = (M + BM - 1) / BM;

    // --- pre layer (tf32, K=256) + dist0 ---
    tf32_gemm_kernel<<<G, 256, GEMM_SMEM>>>(x, pre_W, FIN, pre_b, hb16, M);
    dist0_kernel<<<(M + D0_ROWS - 1) / D0_ROWS, 128>>>(edge_attr, d_W0, d_b0, y0b16, M);

    // --- agg1 ---
    mean_agg_kernel<<<(M * 16 + 255) / 256, 256>>>(hb16, aggb16, M);

    // --- layer1 conv (c1) + dist layer1 (d1), batched, relu'd bf16 outs ---
    bf16_gemm_dual<<<2 * G, 256>>>(
        hb16, wt_c1s, aggb16, wt_c1n, c1_b, h2b16, 0,
        y0b16, wt_d1, d_b1, y1b16, 0,
        nullptr, M, G);

    // --- agg2 ---
    mean_agg_kernel<<<(M * 16 + 255) / 256, 256>>>(h2b16, aggb16, M);

    // --- layer2 conv (c2) + dist layer2 (d2), batched, fused final dot ---
    bf16_gemm_dual<<<2 * G, 256>>>(
        h2b16, wt_c2s, aggb16, wt_c2n, c2_b, nullptr, 1,
        y1b16, wt_d2, d_b2, nullptr, 2,
        out, M, G);

    // --- sigmoid ---
    sigmoid_kernel<<<(M + 255) / 256, 256>>>(out, M);
}

// round 9
// speedup vs baseline: 3.4416x; 1.0490x over previous
#include <cuda_runtime.h>
#include <cuda_bf16.h>
#include <math.h>

// ---------------- problem constants ----------------
#define NN  100000
#define HD  128
#define EE  1600000
#define FIN 256
#define KD  5

// ---------------- scratch (static __device__, no allocation) ----------------
__device__ __nv_bfloat16 g_hb16 [(size_t)NN * HD];
__device__ __nv_bfloat16 g_h2b16[(size_t)NN * HD];
__device__ __nv_bfloat16 g_aggb16[(size_t)NN * HD];
__device__ __nv_bfloat16 g_y0b16[(size_t)NN * HD];
__device__ __nv_bfloat16 g_y1b16[(size_t)NN * HD];
__device__ __nv_bfloat16 g_wt[6 * HD * HD];   // transposed bf16 weights [n][k]

__device__ int g_csr_src[EE];
__device__ int g_counts[NN];
__device__ int g_incl[NN];
__device__ int g_offs[NN + 1];
__device__ int g_cursor[NN];
__device__ int g_bsum[256];
__device__ int g_flag64;

// folded final-layer vectors: out = sigmoid(h_final . vfeat + y2 . vdist + cc)
__device__ float g_vfeat[HD];
__device__ float g_vdist[HD];
__device__ float g_cc;

// ---------------- zero counts + out, and detect edge-index dtype ----------------
// int64 little-endian with values < 2^31 => every odd 32-bit word of the first
// 32 elements is zero; for int32 those words are random indices.
__global__ void zero_detect_kernel(float* __restrict__ out, int n,
                                   const unsigned* __restrict__ ei) {
    int i = blockIdx.x * blockDim.x + threadIdx.x;
    if (i < n) { g_counts[i] = 0; out[i] = 0.f; }
    if (blockIdx.x == 0 && threadIdx.x == 0) {
        unsigned any = 0;
#pragma unroll
        for (int j = 1; j < 64; j += 2) any |= ei[j];
        g_flag64 = (any == 0) ? 1 : 0;
    }
}

// histogram from edge_index dst half (32-bit reads only)
__global__ void histogram_kernel(const int* __restrict__ p32, int E) {
    int i = blockIdx.x * blockDim.x + threadIdx.x;
    if (i >= E) return;
    int d = g_flag64 ? p32[2 * ((size_t)E + i)] : p32[E + i];
    atomicAdd(&g_counts[d], 1);
}

__global__ void scan1_kernel(int n) {
    __shared__ int s[1024];
    int i = blockIdx.x * 1024 + threadIdx.x;
    int v = (i < n) ? g_counts[i] : 0;
    s[threadIdx.x] = v;
    __syncthreads();
#pragma unroll
    for (int off = 1; off < 1024; off <<= 1) {
        int t = (threadIdx.x >= off) ? s[threadIdx.x - off] : 0;
        __syncthreads();
        s[threadIdx.x] += t;
        __syncthreads();
    }
    if (i < n) g_incl[i] = s[threadIdx.x];
    if (threadIdx.x == 1023) g_bsum[blockIdx.x] = s[1023];
}

__global__ void scan2_kernel(int nb) {
    if (threadIdx.x == 0 && blockIdx.x == 0) {
        int run = 0;
        for (int i = 0; i < nb; ++i) {
            int v = g_bsum[i];
            g_bsum[i] = run;
            run += v;
        }
    }
}

__global__ void scan3_kernel(int n, int E) {
    int i = blockIdx.x * blockDim.x + threadIdx.x;
    if (i >= n) return;
    int off = g_bsum[i >> 10] + g_incl[i] - g_counts[i];
    g_offs[i] = off;
    g_cursor[i] = off;
    if (i == n - 1) g_offs[n] = E;
}

// scatter from edge_index (32-bit reads only)
__global__ void scatter_csr_kernel(const int* __restrict__ p32, int E) {
    int i = blockIdx.x * blockDim.x + threadIdx.x;
    if (i >= E) return;
    int s, d;
    if (g_flag64) {
        s = p32[2 * (size_t)i];
        d = p32[2 * ((size_t)E + i)];
    } else {
        s = p32[i];
        d = p32[E + i];
    }
    int pos = atomicAdd(&g_cursor[d], 1);
    g_csr_src[pos] = s;
}

// ---------------- prep: fold final layers (block 0) + weight transpose (blocks 1+) ----------------
__global__ void prep_kernel(
    const float* __restrict__ np_W, const float* __restrict__ np_b,
    const float* __restrict__ d_W3, const float* __restrict__ d_b3,
    const float* __restrict__ fW, const float* __restrict__ fb,
    const float* __restrict__ w0, const float* __restrict__ w1,
    const float* __restrict__ w2, const float* __restrict__ w3,
    const float* __restrict__ w4, const float* __restrict__ w5)
{
    if (blockIdx.x == 0) {
        int j = threadIdx.x;
        if (j < HD) {
            float vf = 0.f, vd = 0.f;
#pragma unroll 8
            for (int k = 0; k < HD; ++k) {
                vf += np_W[j * HD + k] * fW[k];
                vd += d_W3[j * HD + k] * fW[HD + k];
            }
            g_vfeat[j] = vf;
            g_vdist[j] = vd;
            if (j == 0) {
                float c = fb[0];
                for (int k = 0; k < HD; ++k)
                    c += np_b[k] * fW[k] + d_b3[k] * fW[HD + k];
                g_cc = c;
            }
        }
        return;
    }
    int i = (blockIdx.x - 1) * 256 + threadIdx.x;     // 6*16384
    if (i >= 6 * HD * HD) return;
    int m = i >> 14;
    int r = i & (HD * HD - 1);
    int n = r >> 7;
    int k = r & 127;
    const float* src = (m == 0) ? w0 : (m == 1) ? w1 : (m == 2) ? w2
                     : (m == 3) ? w3 : (m == 4) ? w4 : w5;
    g_wt[i] = __float2bfloat16(src[k * HD + n]);
}

// ---------------- mean aggregation: 16 lanes/node, uint4 bf16 gather ----------------
__global__ void mean_agg_kernel(const __nv_bfloat16* __restrict__ h16,
                                __nv_bfloat16* __restrict__ agg16, int n) {
    int idx = blockIdx.x * blockDim.x + threadIdx.x;
    int node = idx >> 4;
    int lane = idx & 15;
    if (node >= n) return;
    int s = g_offs[node];
    int e = g_offs[node + 1];
    float a0 = 0.f, a1 = 0.f, a2 = 0.f, a3 = 0.f,
          a4 = 0.f, a5 = 0.f, a6 = 0.f, a7 = 0.f;
    int i = s;
    for (; i + 4 <= e; i += 4) {
        int s0 = __ldg(&g_csr_src[i]);
        int s1 = __ldg(&g_csr_src[i + 1]);
        int s2 = __ldg(&g_csr_src[i + 2]);
        int s3 = __ldg(&g_csr_src[i + 3]);
        uint4 u0 = ((const uint4*)(h16 + (size_t)s0 * HD))[lane];
        uint4 u1 = ((const uint4*)(h16 + (size_t)s1 * HD))[lane];
        uint4 u2 = ((const uint4*)(h16 + (size_t)s2 * HD))[lane];
        uint4 u3 = ((const uint4*)(h16 + (size_t)s3 * HD))[lane];
        float2 p;
#define ACC8(u) \
        p = __bfloat1622float2(*(__nv_bfloat162*)&(u).x); a0 += p.x; a1 += p.y; \
        p = __bfloat1622float2(*(__nv_bfloat162*)&(u).y); a2 += p.x; a3 += p.y; \
        p = __bfloat1622float2(*(__nv_bfloat162*)&(u).z); a4 += p.x; a5 += p.y; \
        p = __bfloat1622float2(*(__nv_bfloat162*)&(u).w); a6 += p.x; a7 += p.y;
        ACC8(u0); ACC8(u1); ACC8(u2); ACC8(u3);
    }
    for (; i < e; ++i) {
        int s0 = __ldg(&g_csr_src[i]);
        uint4 u0 = ((const uint4*)(h16 + (size_t)s0 * HD))[lane];
        float2 p;
        ACC8(u0);
    }
#undef ACC8
    float inv = 1.0f / (float)max(e - s, 1);
    uint4 r;
    *(__nv_bfloat162*)&r.x = __float22bfloat162_rn(make_float2(a0 * inv, a1 * inv));
    *(__nv_bfloat162*)&r.y = __float22bfloat162_rn(make_float2(a2 * inv, a3 * inv));
    *(__nv_bfloat162*)&r.z = __float22bfloat162_rn(make_float2(a4 * inv, a5 * inv));
    *(__nv_bfloat162*)&r.w = __float22bfloat162_rn(make_float2(a6 * inv, a7 * inv));
    ((uint4*)(agg16 + (size_t)node * HD))[lane] = r;
}

// ================= common helpers =================
__device__ __forceinline__ unsigned smem_u32p(const void* p) {
    return (unsigned)__cvta_generic_to_shared(p);
}
__device__ __forceinline__ void cp_async16(unsigned dst, const void* src, int pred) {
    asm volatile("cp.async.cg.shared.global [%0], [%1], 16, %2;\n"
                 :: "r"(dst), "l"(src), "r"(pred ? 16 : 0));
}

// ---------------- TF32 GEMM (pre layer, K=256), cp.async 2-stage, 2 CTA/SM ----------------
#define BM 128
#define BN 128
#define BK 32
#define SA 36
#define SB 136
#define STAGE_FLOATS 8960
#define GEMM_SMEM   (2 * STAGE_FLOATS * 4)

__device__ __forceinline__ void gemm_load_tile(
    float* As, float* Bs, const float* __restrict__ A, const float* __restrict__ W,
    int K, int k0, int row0, int M, int tid)
{
#pragma unroll
    for (int i = 0; i < 4; ++i) {
        int c = tid + i * 256;
        int r = c >> 3;
        int off = (c & 7) * 4;
        int gr = row0 + r;
        cp_async16(smem_u32p(As + r * SA + off),
                   A + (size_t)gr * K + k0 + off, gr < M);
    }
#pragma unroll
    for (int i = 0; i < 4; ++i) {
        int c = tid + i * 256;
        int r = c >> 5;
        int off = (c & 31) * 4;
        cp_async16(smem_u32p(Bs + r * SB + off),
                   W + (size_t)(k0 + r) * BN + off, 1);
    }
    asm volatile("cp.async.commit_group;\n" ::);
}

__device__ __forceinline__ void mma_tf32(float* c, const unsigned* a, const unsigned* b) {
    asm volatile(
        "mma.sync.aligned.m16n8k8.row.col.f32.tf32.tf32.f32 "
        "{%0,%1,%2,%3}, {%4,%5,%6,%7}, {%8,%9}, {%0,%1,%2,%3};"
        : "+f"(c[0]), "+f"(c[1]), "+f"(c[2]), "+f"(c[3])
        : "r"(a[0]), "r"(a[1]), "r"(a[2]), "r"(a[3]), "r"(b[0]), "r"(b[1]));
}

__global__ void __launch_bounds__(256, 2) tf32_gemm_kernel(
    const float* __restrict__ A1, const float* __restrict__ W1, int K1,
    const float* __restrict__ bias, __nv_bfloat16* __restrict__ C16, int M)
{
    extern __shared__ float sm[];
    float* AsB[2] = { sm,            sm + STAGE_FLOATS };
    float* BsB[2] = { sm + 128 * SA, sm + STAGE_FLOATS + 128 * SA };

    int tid = threadIdx.x;
    int lane = tid & 31;
    int warp = tid >> 5;
    int wm = (warp >> 2) * 64;
    int wn = (warp & 3) * 32;
    int row0 = blockIdx.x * BM;
    int g = lane >> 2;
    int q = lane & 3;

    float acc[4][4][4];
#pragma unroll
    for (int i = 0; i < 4; ++i)
#pragma unroll
        for (int j = 0; j < 4; ++j)
#pragma unroll
            for (int k = 0; k < 4; ++k) acc[i][j][k] = 0.f;

    int total = K1 >> 5;
    gemm_load_tile(AsB[0], BsB[0], A1, W1, K1, 0, row0, M, tid);

    for (int t = 0; t < total; ++t) {
        if (t + 1 < total) {
            gemm_load_tile(AsB[(t + 1) & 1], BsB[(t + 1) & 1], A1, W1, K1,
                           (t + 1) * BK, row0, M, tid);
            asm volatile("cp.async.wait_group 1;\n" ::);
        } else {
            asm volatile("cp.async.wait_group 0;\n" ::);
        }
        __syncthreads();

        const float* As = AsB[t & 1];
        const float* Bs = BsB[t & 1];
#pragma unroll
        for (int kk = 0; kk < BK; kk += 8) {
            int kq = kk + q;
            unsigned a[4][4], b[4][2];
#pragma unroll
            for (int fm = 0; fm < 4; ++fm) {
                int m = wm + fm * 16 + g;
                a[fm][0] = __float_as_uint(As[m * SA + kq]);
                a[fm][1] = __float_as_uint(As[(m + 8) * SA + kq]);
                a[fm][2] = __float_as_uint(As[m * SA + kq + 4]);
                a[fm][3] = __float_as_uint(As[(m + 8) * SA + kq + 4]);
            }
#pragma unroll
            for (int fn = 0; fn < 4; ++fn) {
                int n = wn + fn * 8 + g;
                b[fn][0] = __float_as_uint(Bs[kq * SB + n]);
                b[fn][1] = __float_as_uint(Bs[(kq + 4) * SB + n]);
            }
#pragma unroll
            for (int fm = 0; fm < 4; ++fm)
#pragma unroll
                for (int fn = 0; fn < 4; ++fn)
                    mma_tf32(acc[fm][fn], a[fm], b[fn]);
        }
        __syncthreads();
    }

#pragma unroll
    for (int fm = 0; fm < 4; ++fm) {
#pragma unroll
        for (int fn = 0; fn < 4; ++fn) {
            int r = row0 + wm + fm * 16 + g;
            int c = wn + fn * 8 + (q << 1);
            float b0 = bias[c], b1 = bias[c + 1];
            float v0 = acc[fm][fn][0] + b0;
            float v1 = acc[fm][fn][1] + b1;
            float v2 = acc[fm][fn][2] + b0;
            float v3 = acc[fm][fn][3] + b1;
            if (r < M)
                *(__nv_bfloat162*)(C16 + (size_t)r * BN + c) =
                    __float22bfloat162_rn(make_float2(v0, v1));
            if (r + 8 < M)
                *(__nv_bfloat162*)(C16 + (size_t)(r + 8) * BN + c) =
                    __float22bfloat162_rn(make_float2(v2, v3));
        }
    }
}

// ---------------- BF16 GEMM (K=128 per source), dual-problem batched ----------------
// fold: 0=store bf16 C16, 1=dot with g_vfeat into out, 2=dot with g_vdist into out
#define SAH 40

__device__ __forceinline__ void bf16_load_tile(
    __nv_bfloat16* As, __nv_bfloat16* Bs,
    const __nv_bfloat16* __restrict__ A, const __nv_bfloat16* __restrict__ Wt,
    int k0, int row0, int M, int tid)
{
#pragma unroll
    for (int i = 0; i < 2; ++i) {
        int c = tid + i * 256;
        int r = c >> 2;
        int j = c & 3;
        int gr = row0 + r;
        cp_async16(smem_u32p(As + r * SAH + j * 8),
                   A + (size_t)gr * HD + k0 + j * 8, gr < M);
    }
#pragma unroll
    for (int i = 0; i < 2; ++i) {
        int c = tid + i * 256;
        int r = c >> 2;
        int j = c & 3;
        cp_async16(smem_u32p(Bs + r * SAH + j * 8),
                   Wt + (size_t)r * HD + k0 + j * 8, 1);
    }
    asm volatile("cp.async.commit_group;\n" ::);
}

__device__ __forceinline__ void mma_bf16(float* c, const unsigned* a, const unsigned* b) {
    asm volatile(
        "mma.sync.aligned.m16n8k16.row.col.f32.bf16.bf16.f32 "
        "{%0,%1,%2,%3}, {%4,%5,%6,%7}, {%8,%9}, {%0,%1,%2,%3};"
        : "+f"(c[0]), "+f"(c[1]), "+f"(c[2]), "+f"(c[3])
        : "r"(a[0]), "r"(a[1]), "r"(a[2]), "r"(a[3]), "r"(b[0]), "r"(b[1]));
}

__global__ void __launch_bounds__(256, 2) bf16_gemm_dual(
    const __nv_bfloat16* __restrict__ A1a, const __nv_bfloat16* __restrict__ Wt1a,
    const __nv_bfloat16* __restrict__ A2a, const __nv_bfloat16* __restrict__ Wt2a,
    const float* __restrict__ biasa, __nv_bfloat16* __restrict__ C16a, int foldA,
    const __nv_bfloat16* __restrict__ A1b, const __nv_bfloat16* __restrict__ Wt1b,
    const float* __restrict__ biasb, __nv_bfloat16* __restrict__ C16b, int foldB,
    float* __restrict__ out, int M, int grid1)
{
    __shared__ __nv_bfloat16 smA[2][128 * SAH];
    __shared__ __nv_bfloat16 smB[2][128 * SAH];
    __shared__ float sfv[BM];
    __shared__ float sred[BM];

    int tid = threadIdx.x;
    int lane = tid & 31;
    int warp = tid >> 5;
    int wm = (warp >> 2) * 64;
    int wn = (warp & 3) * 32;
    int g = lane >> 2;
    int q = lane & 3;

    int probB = (blockIdx.x >= grid1);
    int row0 = (probB ? (blockIdx.x - grid1) : blockIdx.x) * BM;

    const __nv_bfloat16* Asrc[2];
    const __nv_bfloat16* Wsrc[2];
    int nsrc;
    const float* bias;
    __nv_bfloat16* C16;
    int fold;
    if (probB) {
        Asrc[0] = A1b; Wsrc[0] = Wt1b; Asrc[1] = A1b; Wsrc[1] = Wt1b;
        nsrc = 1; bias = biasb; C16 = C16b; fold = foldB;
    } else {
        Asrc[0] = A1a; Wsrc[0] = Wt1a; Asrc[1] = A2a; Wsrc[1] = Wt2a;
        nsrc = A2a ? 2 : 1; bias = biasa; C16 = C16a; fold = foldA;
    }

    if (fold && tid < BM) {
        sfv[tid] = (fold == 1) ? g_vfeat[tid] : g_vdist[tid];
        sred[tid] = 0.f;
    }

    float acc[4][4][4];
#pragma unroll
    for (int i = 0; i < 4; ++i)
#pragma unroll
        for (int j = 0; j < 4; ++j)
#pragma unroll
            for (int k = 0; k < 4; ++k) acc[i][j][k] = 0.f;

    int total = nsrc * 4;
    bf16_load_tile(smA[0], smB[0], Asrc[0], Wsrc[0], 0, row0, M, tid);

    for (int t = 0; t < total; ++t) {
        if (t + 1 < total) {
            int p = (t + 1) >> 2;
            int k0 = ((t + 1) & 3) * BK;
            bf16_load_tile(smA[(t + 1) & 1], smB[(t + 1) & 1],
                           Asrc[p], Wsrc[p], k0, row0, M, tid);
            asm volatile("cp.async.wait_group 1;\n" ::);
        } else {
            asm volatile("cp.async.wait_group 0;\n" ::);
        }
        __syncthreads();

        const __nv_bfloat16* As = smA[t & 1];
        const __nv_bfloat16* Bs = smB[t & 1];
#pragma unroll
        for (int kk = 0; kk < BK; kk += 16) {
            int kq = kk + 2 * q;
            unsigned a[4][4], b[4][2];
#pragma unroll
            for (int fm = 0; fm < 4; ++fm) {
                int m = wm + fm * 16 + g;
                a[fm][0] = *(const unsigned*)&As[m * SAH + kq];
                a[fm][1] = *(const unsigned*)&As[(m + 8) * SAH + kq];
                a[fm][2] = *(const unsigned*)&As[m * SAH + kq + 8];
                a[fm][3] = *(const unsigned*)&As[(m + 8) * SAH + kq + 8];
            }
#pragma unroll
            for (int fn = 0; fn < 4; ++fn) {
                int n = wn + fn * 8 + g;
                b[fn][0] = *(const unsigned*)&Bs[n * SAH + kq];
                b[fn][1] = *(const unsigned*)&Bs[n * SAH + kq + 8];
            }
#pragma unroll
            for (int fm = 0; fm < 4; ++fm)
#pragma unroll
                for (int fn = 0; fn < 4; ++fn)
                    mma_bf16(acc[fm][fn], a[fm], b[fn]);
        }
        __syncthreads();
    }

    if (fold) {
#pragma unroll
        for (int fm = 0; fm < 4; ++fm) {
            float p0 = 0.f, p8 = 0.f;
#pragma unroll
            for (int fn = 0; fn < 4; ++fn) {
                int c = wn + fn * 8 + (q << 1);
                float b0 = bias[c], b1 = bias[c + 1];
                float w0 = sfv[c], w1 = sfv[c + 1];
                p0 += fmaxf(acc[fm][fn][0] + b0, 0.f) * w0
                    + fmaxf(acc[fm][fn][1] + b1, 0.f) * w1;
                p8 += fmaxf(acc[fm][fn][2] + b0, 0.f) * w0
                    + fmaxf(acc[fm][fn][3] + b1, 0.f) * w1;
            }
            atomicAdd(&sred[wm + fm * 16 + g], p0);
            atomicAdd(&sred[wm + fm * 16 + g + 8], p8);
        }
        __syncthreads();
        if (tid < BM) {
            int r = row0 + tid;
            if (r < M) atomicAdd(out + r, sred[tid]);
        }
    } else {
#pragma unroll
        for (int fm = 0; fm < 4; ++fm) {
#pragma unroll
            for (int fn = 0; fn < 4; ++fn) {
                int r = row0 + wm + fm * 16 + g;
                int c = wn + fn * 8 + (q << 1);
                float b0 = bias[c], b1 = bias[c + 1];
                float v0 = fmaxf(acc[fm][fn][0] + b0, 0.f);
                float v1 = fmaxf(acc[fm][fn][1] + b1, 0.f);
                float v2 = fmaxf(acc[fm][fn][2] + b0, 0.f);
                float v3 = fmaxf(acc[fm][fn][3] + b1, 0.f);
                if (r < M)
                    *(__nv_bfloat162*)(C16 + (size_t)r * BN + c) =
                        __float22bfloat162_rn(make_float2(v0, v1));
                if (r + 8 < M)
                    *(__nv_bfloat162*)(C16 + (size_t)(r + 8) * BN + c) =
                        __float22bfloat162_rn(make_float2(v2, v3));
            }
        }
    }
}

// ---------------- dist layer0 : y = relu(e[M,5] @ W0[5,128] + b0) -> bf16 ----------------
#define D0_ROWS 16
__global__ void dist0_kernel(const float* __restrict__ e, const float* __restrict__ W0,
                             const float* __restrict__ b0,
                             __nv_bfloat16* __restrict__ y, int M)
{
    __shared__ float ws[KD * HD];
    for (int i = threadIdx.x; i < KD * HD; i += blockDim.x) ws[i] = W0[i];
    __syncthreads();
    int c = threadIdx.x;
    float bv = b0[c];
    int r0 = blockIdx.x * D0_ROWS;
    for (int rr = 0; rr < D0_ROWS; ++rr) {
        int r = r0 + rr;
        if (r >= M) return;
        float acc = bv;
#pragma unroll
        for (int k = 0; k < KD; ++k)
            acc += e[(size_t)r * KD + k] * ws[k * HD + c];
        y[(size_t)r * HD + c] = __float2bfloat16(fmaxf(acc, 0.f));
    }
}

// ---------------- sigmoid epilogue ----------------
__global__ void sigmoid_kernel(float* __restrict__ out, int M) {
    int i = blockIdx.x * blockDim.x + threadIdx.x;
    if (i >= M) return;
    float v = out[i] + g_cc;
    out[i] = 1.0f / (1.0f + __expf(-v));
}

// ---------------- launch ----------------
extern "C" void kernel_launch(void* const* d_in, const int* in_sizes, int n_in,
                              void* d_out, int out_size)
{
    const float* x          = (const float*)d_in[0];
    const void*  edge_index = d_in[1];
    const float* edge_attr  = (const float*)d_in[2];
    const float* pre_W      = (const float*)d_in[3];
    const float* pre_b      = (const float*)d_in[4];
    const float* c1_Ws      = (const float*)d_in[5];
    const float* c1_Wn      = (const float*)d_in[6];
    const float* c1_b       = (const float*)d_in[7];
    const float* c2_Ws      = (const float*)d_in[8];
    const float* c2_Wn      = (const float*)d_in[9];
    const float* c2_b       = (const float*)d_in[10];
    const float* np_W       = (const float*)d_in[11];
    const float* np_b       = (const float*)d_in[12];
    const float* d_W0       = (const float*)d_in[13];
    const float* d_b0       = (const float*)d_in[14];
    const float* d_W1       = (const float*)d_in[15];
    const float* d_b1       = (const float*)d_in[16];
    const float* d_W2       = (const float*)d_in[17];
    const float* d_b2       = (const float*)d_in[18];
    const float* d_W3       = (const float*)d_in[19];
    const float* d_b3       = (const float*)d_in[20];
    const float* final_W    = (const float*)d_in[21];
    const float* final_b    = (const float*)d_in[22];
    float* out = (float*)d_out;

    int M = NN;
    int E = in_sizes[1] / 2;
    if (E > EE) E = EE;

    __nv_bfloat16 *hb16, *h2b16, *aggb16, *y0b16, *y1b16, *wt;
    cudaGetSymbolAddress((void**)&hb16,   g_hb16);
    cudaGetSymbolAddress((void**)&h2b16,  g_h2b16);
    cudaGetSymbolAddress((void**)&aggb16, g_aggb16);
    cudaGetSymbolAddress((void**)&y0b16,  g_y0b16);
    cudaGetSymbolAddress((void**)&y1b16,  g_y1b16);
    cudaGetSymbolAddress((void**)&wt,     g_wt);

    cudaFuncSetAttribute(tf32_gemm_kernel,
                         cudaFuncAttributeMaxDynamicSharedMemorySize, GEMM_SMEM);

    // --- CSR build (direct from edge_index, 32-bit reads) ---
    zero_detect_kernel<<<(M + 255) / 256, 256>>>(out, M, (const unsigned*)edge_index);
    histogram_kernel<<<(E + 255) / 256, 256>>>((const int*)edge_index, E);
    int nb = (M + 1023) / 1024;
    scan1_kernel<<<nb, 1024>>>(M);
    scan2_kernel<<<1, 32>>>(nb);
    scan3_kernel<<<(M + 255) / 256, 256>>>(M, E);
    scatter_csr_kernel<<<(E + 255) / 256, 256>>>((const int*)edge_index, E);

    // --- constant prep (fold + weight transpose, one launch) ---
    prep_kernel<<<1 + (6 * HD * HD + 255) / 256, 256>>>(
        np_W, np_b, d_W3, d_b3, final_W, final_b,
        c1_Ws, c1_Wn, c2_Ws, c2_Wn, d_W1, d_W2);

    const __nv_bfloat16* wt_c1s = wt + 0 * HD * HD;
    const __nv_bfloat16* wt_c1n = wt + 1 * HD * HD;
    const __nv_bfloat16* wt_c2s = wt + 2 * HD * HD;
    const __nv_bfloat16* wt_c2n = wt + 3 * HD * HD;
    const __nv_bfloat16* wt_d1  = wt + 4 * HD * HD;
    const __nv_bfloat16* wt_d2  = wt + 5 * HD * HD;

    int G = (M + BM - 1) / BM;

    // --- pre layer (tf32, K=256) + dist0 ---
    tf32_gemm_kernel<<<G, 256, GEMM_SMEM>>>(x, pre_W, FIN, pre_b, hb16, M);
    dist0_kernel<<<(M + D0_ROWS - 1) / D0_ROWS, 128>>>(edge_attr, d_W0, d_b0, y0b16, M);

    // --- agg1 ---
    mean_agg_kernel<<<(M * 16 + 255) / 256, 256>>>(hb16, aggb16, M);

    // --- layer1 conv (c1) + dist layer1 (d1), batched, relu'd bf16 outs ---
    bf16_gemm_dual<<<2 * G, 256>>>(
        hb16, wt_c1s, aggb16, wt_c1n, c1_b, h2b16, 0,
        y0b16, wt_d1, d_b1, y1b16, 0,
        nullptr, M, G);

    // --- agg2 ---
    mean_agg_kernel<<<(M * 16 + 255) / 256, 256>>>(h2b16, aggb16, M);

    // --- layer2 conv (c2) + dist layer2 (d2), batched, fused final dot ---
    bf16_gemm_dual<<<2 * G, 256>>>(
        h2b16, wt_c2s, aggb16, wt_c2n, c2_b, nullptr, 1,
        y1b16, wt_d2, d_b2, nullptr, 2,
        out, M, G);

    // --- sigmoid ---
    sigmoid_kernel<<<(M + 255) / 256, 256>>>(out, M);
}

// round 10
// speedup vs baseline: 3.5273x; 1.0249x over previous
#include <cuda_runtime.h>
#include <cuda_bf16.h>
#include <math.h>

// ---------------- problem constants ----------------
#define NN  100000
#define HD  128
#define EE  1600000
#define FIN 256
#define KD  5

// ---------------- scratch (static __device__, no allocation) ----------------
__device__ __nv_bfloat16 g_hb16 [(size_t)NN * HD];
__device__ __nv_bfloat16 g_h2b16[(size_t)NN * HD];
__device__ __nv_bfloat16 g_aggb16[(size_t)NN * HD];
__device__ __nv_bfloat16 g_y0b16[(size_t)NN * HD];
__device__ __nv_bfloat16 g_y1b16[(size_t)NN * HD];
// slots 0..5: HD x HD weights [n][k]; slot 6 (at 6*HD*HD): pre_W^T [128n][256k]
__device__ __nv_bfloat16 g_wt[6 * HD * HD + HD * FIN];

__device__ int g_csr_src[EE];
__device__ int g_counts[NN];
__device__ int g_incl[NN];
__device__ int g_offs[NN + 1];
__device__ int g_cursor[NN];
__device__ int g_bsum[256];
__device__ int g_flag64;

// folded final-layer vectors: out = sigmoid(h_final . vfeat + y2 . vdist + cc)
__device__ float g_vfeat[HD];
__device__ float g_vdist[HD];
__device__ float g_cc;

// ---------------- zero counts + out, and detect edge-index dtype ----------------
__global__ void zero_detect_kernel(float* __restrict__ out, int n,
                                   const unsigned* __restrict__ ei) {
    int i = blockIdx.x * blockDim.x + threadIdx.x;
    if (i < n) { g_counts[i] = 0; out[i] = 0.f; }
    if (blockIdx.x == 0 && threadIdx.x == 0) {
        unsigned any = 0;
#pragma unroll
        for (int j = 1; j < 64; j += 2) any |= ei[j];
        g_flag64 = (any == 0) ? 1 : 0;
    }
}

// histogram from edge_index dst half (32-bit reads only)
__global__ void histogram_kernel(const int* __restrict__ p32, int E) {
    int i = blockIdx.x * blockDim.x + threadIdx.x;
    if (i >= E) return;
    int d = g_flag64 ? p32[2 * ((size_t)E + i)] : p32[E + i];
    atomicAdd(&g_counts[d], 1);
}

__global__ void scan1_kernel(int n) {
    __shared__ int s[1024];
    int i = blockIdx.x * 1024 + threadIdx.x;
    int v = (i < n) ? g_counts[i] : 0;
    s[threadIdx.x] = v;
    __syncthreads();
#pragma unroll
    for (int off = 1; off < 1024; off <<= 1) {
        int t = (threadIdx.x >= off) ? s[threadIdx.x - off] : 0;
        __syncthreads();
        s[threadIdx.x] += t;
        __syncthreads();
    }
    if (i < n) g_incl[i] = s[threadIdx.x];
    if (threadIdx.x == 1023) g_bsum[blockIdx.x] = s[1023];
}

// parallel exclusive scan over <=128 block sums
__global__ void scan2_kernel(int nb) {
    __shared__ int s[128];
    int t = threadIdx.x;
    int v = (t < nb) ? g_bsum[t] : 0;
    s[t] = v;
    __syncthreads();
#pragma unroll
    for (int off = 1; off < 128; off <<= 1) {
        int u = (t >= off) ? s[t - off] : 0;
        __syncthreads();
        s[t] += u;
        __syncthreads();
    }
    if (t < nb) g_bsum[t] = s[t] - v;   // exclusive
}

__global__ void scan3_kernel(int n, int E) {
    int i = blockIdx.x * blockDim.x + threadIdx.x;
    if (i >= n) return;
    int off = g_bsum[i >> 10] + g_incl[i] - g_counts[i];
    g_offs[i] = off;
    g_cursor[i] = off;
    if (i == n - 1) g_offs[n] = E;
}

// scatter from edge_index (32-bit reads only)
__global__ void scatter_csr_kernel(const int* __restrict__ p32, int E) {
    int i = blockIdx.x * blockDim.x + threadIdx.x;
    if (i >= E) return;
    int s, d;
    if (g_flag64) {
        s = p32[2 * (size_t)i];
        d = p32[2 * ((size_t)E + i)];
    } else {
        s = p32[i];
        d = p32[E + i];
    }
    int pos = atomicAdd(&g_cursor[d], 1);
    g_csr_src[pos] = s;
}

// ---------------- prep: fold (block 0) + weight transposes (blocks 1+) ----------------
__global__ void prep_kernel(
    const float* __restrict__ np_W, const float* __restrict__ np_b,
    const float* __restrict__ d_W3, const float* __restrict__ d_b3,
    const float* __restrict__ fW, const float* __restrict__ fb,
    const float* __restrict__ w0, const float* __restrict__ w1,
    const float* __restrict__ w2, const float* __restrict__ w3,
    const float* __restrict__ w4, const float* __restrict__ w5,
    const float* __restrict__ preW)
{
    if (blockIdx.x == 0) {
        int j = threadIdx.x;
        if (j < HD) {
            float vf = 0.f, vd = 0.f;
#pragma unroll 8
            for (int k = 0; k < HD; ++k) {
                vf += np_W[j * HD + k] * fW[k];
                vd += d_W3[j * HD + k] * fW[HD + k];
            }
            g_vfeat[j] = vf;
            g_vdist[j] = vd;
            if (j == 0) {
                float c = fb[0];
                for (int k = 0; k < HD; ++k)
                    c += np_b[k] * fW[k] + d_b3[k] * fW[HD + k];
                g_cc = c;
            }
        }
        return;
    }
    int i = (blockIdx.x - 1) * 256 + threadIdx.x;
    if (i < 6 * HD * HD) {
        int m = i >> 14;
        int r = i & (HD * HD - 1);
        int n = r >> 7;
        int k = r & 127;
        const float* src = (m == 0) ? w0 : (m == 1) ? w1 : (m == 2) ? w2
                         : (m == 3) ? w3 : (m == 4) ? w4 : w5;
        g_wt[i] = __float2bfloat16(src[k * HD + n]);
    } else if (i < 6 * HD * HD + HD * FIN) {
        int j = i - 6 * HD * HD;     // n*256 + k
        int n = j >> 8;
        int k = j & 255;
        g_wt[i] = __float2bfloat16(preW[k * HD + n]);
    }
}

// ---------------- mean aggregation: 16 lanes/node, uint4 bf16 gather ----------------
__global__ void mean_agg_kernel(const __nv_bfloat16* __restrict__ h16,
                                __nv_bfloat16* __restrict__ agg16, int n) {
    int idx = blockIdx.x * blockDim.x + threadIdx.x;
    int node = idx >> 4;
    int lane = idx & 15;
    if (node >= n) return;
    int s = g_offs[node];
    int e = g_offs[node + 1];
    float a0 = 0.f, a1 = 0.f, a2 = 0.f, a3 = 0.f,
          a4 = 0.f, a5 = 0.f, a6 = 0.f, a7 = 0.f;
    int i = s;
    for (; i + 4 <= e; i += 4) {
        int s0 = __ldg(&g_csr_src[i]);
        int s1 = __ldg(&g_csr_src[i + 1]);
        int s2 = __ldg(&g_csr_src[i + 2]);
        int s3 = __ldg(&g_csr_src[i + 3]);
        uint4 u0 = ((const uint4*)(h16 + (size_t)s0 * HD))[lane];
        uint4 u1 = ((const uint4*)(h16 + (size_t)s1 * HD))[lane];
        uint4 u2 = ((const uint4*)(h16 + (size_t)s2 * HD))[lane];
        uint4 u3 = ((const uint4*)(h16 + (size_t)s3 * HD))[lane];
        float2 p;
#define ACC8(u) \
        p = __bfloat1622float2(*(__nv_bfloat162*)&(u).x); a0 += p.x; a1 += p.y; \
        p = __bfloat1622float2(*(__nv_bfloat162*)&(u).y); a2 += p.x; a3 += p.y; \
        p = __bfloat1622float2(*(__nv_bfloat162*)&(u).z); a4 += p.x; a5 += p.y; \
        p = __bfloat1622float2(*(__nv_bfloat162*)&(u).w); a6 += p.x; a7 += p.y;
        ACC8(u0); ACC8(u1); ACC8(u2); ACC8(u3);
    }
    for (; i < e; ++i) {
        int s0 = __ldg(&g_csr_src[i]);
        uint4 u0 = ((const uint4*)(h16 + (size_t)s0 * HD))[lane];
        float2 p;
        ACC8(u0);
    }
#undef ACC8
    float inv = 1.0f / (float)max(e - s, 1);
    uint4 r;
    *(__nv_bfloat162*)&r.x = __float22bfloat162_rn(make_float2(a0 * inv, a1 * inv));
    *(__nv_bfloat162*)&r.y = __float22bfloat162_rn(make_float2(a2 * inv, a3 * inv));
    *(__nv_bfloat162*)&r.z = __float22bfloat162_rn(make_float2(a4 * inv, a5 * inv));
    *(__nv_bfloat162*)&r.w = __float22bfloat162_rn(make_float2(a6 * inv, a7 * inv));
    ((uint4*)(agg16 + (size_t)node * HD))[lane] = r;
}

// ================= common helpers =================
__device__ __forceinline__ unsigned smem_u32p(const void* p) {
    return (unsigned)__cvta_generic_to_shared(p);
}
__device__ __forceinline__ void cp_async16(unsigned dst, const void* src, int pred) {
    asm volatile("cp.async.cg.shared.global [%0], [%1], 16, %2;\n"
                 :: "r"(dst), "l"(src), "r"(pred ? 16 : 0));
}
__device__ __forceinline__ void mma_bf16(float* c, const unsigned* a, const unsigned* b) {
    asm volatile(
        "mma.sync.aligned.m16n8k16.row.col.f32.bf16.bf16.f32 "
        "{%0,%1,%2,%3}, {%4,%5,%6,%7}, {%8,%9}, {%0,%1,%2,%3};"
        : "+f"(c[0]), "+f"(c[1]), "+f"(c[2]), "+f"(c[3])
        : "r"(a[0]), "r"(a[1]), "r"(a[2]), "r"(a[3]), "r"(b[0]), "r"(b[1]));
}

#define BM 128
#define BN 128
#define BK 32

// ---------------- PRE GEMM: A fp32 gmem, Wt bf16 [n][256k], bf16 MMA ----------------
// A fp32 tile [128][PSA]; convert to bf16 at fragment load (float2 -> bf16x2).
#define PSA 36   // fp32 A stride
#define PSB 40   // bf16 B stride
#define PRE_STAGE_BYTES (128 * PSA * 4 + 128 * PSB * 2)   // 18432 + 10240 = 28672
#define PRE_SMEM (2 * PRE_STAGE_BYTES)                    // 57344

__device__ __forceinline__ void pre_load_tile(
    float* As, __nv_bfloat16* Bs,
    const float* __restrict__ A, const __nv_bfloat16* __restrict__ Wt,
    int k0, int row0, int M, int tid)
{
    // A tile: 128 rows x 32 fp32 (128 B/row) = 1024 x 16B chunks
#pragma unroll
    for (int i = 0; i < 4; ++i) {
        int c = tid + i * 256;
        int r = c >> 3;
        int off = (c & 7) * 4;
        int gr = row0 + r;
        cp_async16(smem_u32p(As + r * PSA + off),
                   A + (size_t)gr * FIN + k0 + off, gr < M);
    }
    // B tile: 128 n-rows x 32 k bf16 (64 B/row) = 512 x 16B chunks
#pragma unroll
    for (int i = 0; i < 2; ++i) {
        int c = tid + i * 256;
        int r = c >> 2;
        int j = c & 3;
        cp_async16(smem_u32p(Bs + r * PSB + j * 8),
                   Wt + (size_t)r * FIN + k0 + j * 8, 1);
    }
    asm volatile("cp.async.commit_group;\n" ::);
}

__global__ void __launch_bounds__(256, 2) pre_gemm_kernel(
    const float* __restrict__ A, const __nv_bfloat16* __restrict__ Wt,
    const float* __restrict__ bias, __nv_bfloat16* __restrict__ C16, int M)
{
    extern __shared__ char smraw[];
    float* AsB[2] = { (float*)smraw, (float*)(smraw + PRE_STAGE_BYTES) };
    __nv_bfloat16* BsB[2] = {
        (__nv_bfloat16*)(smraw + 128 * PSA * 4),
        (__nv_bfloat16*)(smraw + PRE_STAGE_BYTES + 128 * PSA * 4) };

    int tid = threadIdx.x;
    int lane = tid & 31;
    int warp = tid >> 5;
    int wm = (warp >> 2) * 64;
    int wn = (warp & 3) * 32;
    int row0 = blockIdx.x * BM;
    int g = lane >> 2;
    int q = lane & 3;

    float acc[4][4][4];
#pragma unroll
    for (int i = 0; i < 4; ++i)
#pragma unroll
        for (int j = 0; j < 4; ++j)
#pragma unroll
            for (int k = 0; k < 4; ++k) acc[i][j][k] = 0.f;

    int total = FIN / BK;   // 8
    pre_load_tile(AsB[0], BsB[0], A, Wt, 0, row0, M, tid);

    for (int t = 0; t < total; ++t) {
        if (t + 1 < total) {
            pre_load_tile(AsB[(t + 1) & 1], BsB[(t + 1) & 1], A, Wt,
                          (t + 1) * BK, row0, M, tid);
            asm volatile("cp.async.wait_group 1;\n" ::);
        } else {
            asm volatile("cp.async.wait_group 0;\n" ::);
        }
        __syncthreads();

        const float* As = AsB[t & 1];
        const __nv_bfloat16* Bs = BsB[t & 1];
#pragma unroll
        for (int kk = 0; kk < BK; kk += 16) {
            int kq = kk + 2 * q;
            unsigned a[4][4], b[4][2];
#pragma unroll
            for (int fm = 0; fm < 4; ++fm) {
                int m = wm + fm * 16 + g;
                float2 f;
                f = *(const float2*)&As[m * PSA + kq];
                a[fm][0] = __float_as_uint(__uint_as_float(0)); // placeholder avoided below
                *(__nv_bfloat162*)&a[fm][0] = __float22bfloat162_rn(f);
                f = *(const float2*)&As[(m + 8) * PSA + kq];
                *(__nv_bfloat162*)&a[fm][1] = __float22bfloat162_rn(f);
                f = *(const float2*)&As[m * PSA + kq + 8];
                *(__nv_bfloat162*)&a[fm][2] = __float22bfloat162_rn(f);
                f = *(const float2*)&As[(m + 8) * PSA + kq + 8];
                *(__nv_bfloat162*)&a[fm][3] = __float22bfloat162_rn(f);
            }
#pragma unroll
            for (int fn = 0; fn < 4; ++fn) {
                int n = wn + fn * 8 + g;
                b[fn][0] = *(const unsigned*)&Bs[n * PSB + kq];
                b[fn][1] = *(const unsigned*)&Bs[n * PSB + kq + 8];
            }
#pragma unroll
            for (int fm = 0; fm < 4; ++fm)
#pragma unroll
                for (int fn = 0; fn < 4; ++fn)
                    mma_bf16(acc[fm][fn], a[fm], b[fn]);
        }
        __syncthreads();
    }

#pragma unroll
    for (int fm = 0; fm < 4; ++fm) {
#pragma unroll
        for (int fn = 0; fn < 4; ++fn) {
            int r = row0 + wm + fm * 16 + g;
            int c = wn + fn * 8 + (q << 1);
            float b0 = bias[c], b1 = bias[c + 1];
            float v0 = acc[fm][fn][0] + b0;
            float v1 = acc[fm][fn][1] + b1;
            float v2 = acc[fm][fn][2] + b0;
            float v3 = acc[fm][fn][3] + b1;
            if (r < M)
                *(__nv_bfloat162*)(C16 + (size_t)r * BN + c) =
                    __float22bfloat162_rn(make_float2(v0, v1));
            if (r + 8 < M)
                *(__nv_bfloat162*)(C16 + (size_t)(r + 8) * BN + c) =
                    __float22bfloat162_rn(make_float2(v2, v3));
        }
    }
}

// ---------------- BF16 GEMM (K=128 per source), dual-problem batched ----------------
// fold: 0=store bf16 C16, 1=dot with g_vfeat into out, 2=dot with g_vdist into out
#define SAH 40

__device__ __forceinline__ void bf16_load_tile(
    __nv_bfloat16* As, __nv_bfloat16* Bs,
    const __nv_bfloat16* __restrict__ A, const __nv_bfloat16* __restrict__ Wt,
    int k0, int row0, int M, int tid)
{
#pragma unroll
    for (int i = 0; i < 2; ++i) {
        int c = tid + i * 256;
        int r = c >> 2;
        int j = c & 3;
        int gr = row0 + r;
        cp_async16(smem_u32p(As + r * SAH + j * 8),
                   A + (size_t)gr * HD + k0 + j * 8, gr < M);
    }
#pragma unroll
    for (int i = 0; i < 2; ++i) {
        int c = tid + i * 256;
        int r = c >> 2;
        int j = c & 3;
        cp_async16(smem_u32p(Bs + r * SAH + j * 8),
                   Wt + (size_t)r * HD + k0 + j * 8, 1);
    }
    asm volatile("cp.async.commit_group;\n" ::);
}

__global__ void __launch_bounds__(256, 2) bf16_gemm_dual(
    const __nv_bfloat16* __restrict__ A1a, const __nv_bfloat16* __restrict__ Wt1a,
    const __nv_bfloat16* __restrict__ A2a, const __nv_bfloat16* __restrict__ Wt2a,
    const float* __restrict__ biasa, __nv_bfloat16* __restrict__ C16a, int foldA,
    const __nv_bfloat16* __restrict__ A1b, const __nv_bfloat16* __restrict__ Wt1b,
    const float* __restrict__ biasb, __nv_bfloat16* __restrict__ C16b, int foldB,
    float* __restrict__ out, int M, int grid1)
{
    __shared__ __nv_bfloat16 smA[2][128 * SAH];
    __shared__ __nv_bfloat16 smB[2][128 * SAH];
    __shared__ float sfv[BM];
    __shared__ float sred[BM];

    int tid = threadIdx.x;
    int lane = tid & 31;
    int warp = tid >> 5;
    int wm = (warp >> 2) * 64;
    int wn = (warp & 3) * 32;
    int g = lane >> 2;
    int q = lane & 3;

    int probB = (blockIdx.x >= grid1);
    int row0 = (probB ? (blockIdx.x - grid1) : blockIdx.x) * BM;

    const __nv_bfloat16* Asrc[2];
    const __nv_bfloat16* Wsrc[2];
    int nsrc;
    const float* bias;
    __nv_bfloat16* C16;
    int fold;
    if (probB) {
        Asrc[0] = A1b; Wsrc[0] = Wt1b; Asrc[1] = A1b; Wsrc[1] = Wt1b;
        nsrc = 1; bias = biasb; C16 = C16b; fold = foldB;
    } else {
        Asrc[0] = A1a; Wsrc[0] = Wt1a; Asrc[1] = A2a; Wsrc[1] = Wt2a;
        nsrc = A2a ? 2 : 1; bias = biasa; C16 = C16a; fold = foldA;
    }

    if (fold && tid < BM) {
        sfv[tid] = (fold == 1) ? g_vfeat[tid] : g_vdist[tid];
        sred[tid] = 0.f;
    }

    float acc[4][4][4];
#pragma unroll
    for (int i = 0; i < 4; ++i)
#pragma unroll
        for (int j = 0; j < 4; ++j)
#pragma unroll
            for (int k = 0; k < 4; ++k) acc[i][j][k] = 0.f;

    int total = nsrc * 4;
    bf16_load_tile(smA[0], smB[0], Asrc[0], Wsrc[0], 0, row0, M, tid);

    for (int t = 0; t < total; ++t) {
        if (t + 1 < total) {
            int p = (t + 1) >> 2;
            int k0 = ((t + 1) & 3) * BK;
            bf16_load_tile(smA[(t + 1) & 1], smB[(t + 1) & 1],
                           Asrc[p], Wsrc[p], k0, row0, M, tid);
            asm volatile("cp.async.wait_group 1;\n" ::);
        } else {
            asm volatile("cp.async.wait_group 0;\n" ::);
        }
        __syncthreads();

        const __nv_bfloat16* As = smA[t & 1];
        const __nv_bfloat16* Bs = smB[t & 1];
#pragma unroll
        for (int kk = 0; kk < BK; kk += 16) {
            int kq = kk + 2 * q;
            unsigned a[4][4], b[4][2];
#pragma unroll
            for (int fm = 0; fm < 4; ++fm) {
                int m = wm + fm * 16 + g;
                a[fm][0] = *(const unsigned*)&As[m * SAH + kq];
                a[fm][1] = *(const unsigned*)&As[(m + 8) * SAH + kq];
                a[fm][2] = *(const unsigned*)&As[m * SAH + kq + 8];
                a[fm][3] = *(const unsigned*)&As[(m + 8) * SAH + kq + 8];
            }
#pragma unroll
            for (int fn = 0; fn < 4; ++fn) {
                int n = wn + fn * 8 + g;
                b[fn][0] = *(const unsigned*)&Bs[n * SAH + kq];
                b[fn][1] = *(const unsigned*)&Bs[n * SAH + kq + 8];
            }
#pragma unroll
            for (int fm = 0; fm < 4; ++fm)
#pragma unroll
                for (int fn = 0; fn < 4; ++fn)
                    mma_bf16(acc[fm][fn], a[fm], b[fn]);
        }
        __syncthreads();
    }

    if (fold) {
#pragma unroll
        for (int fm = 0; fm < 4; ++fm) {
            float p0 = 0.f, p8 = 0.f;
#pragma unroll
            for (int fn = 0; fn < 4; ++fn) {
                int c = wn + fn * 8 + (q << 1);
                float b0 = bias[c], b1 = bias[c + 1];
                float w0 = sfv[c], w1 = sfv[c + 1];
                p0 += fmaxf(acc[fm][fn][0] + b0, 0.f) * w0
                    + fmaxf(acc[fm][fn][1] + b1, 0.f) * w1;
                p8 += fmaxf(acc[fm][fn][2] + b0, 0.f) * w0
                    + fmaxf(acc[fm][fn][3] + b1, 0.f) * w1;
            }
            atomicAdd(&sred[wm + fm * 16 + g], p0);
            atomicAdd(&sred[wm + fm * 16 + g + 8], p8);
        }
        __syncthreads();
        if (tid < BM) {
            int r = row0 + tid;
            if (r < M) atomicAdd(out + r, sred[tid]);
        }
    } else {
#pragma unroll
        for (int fm = 0; fm < 4; ++fm) {
#pragma unroll
            for (int fn = 0; fn < 4; ++fn) {
                int r = row0 + wm + fm * 16 + g;
                int c = wn + fn * 8 + (q << 1);
                float b0 = bias[c], b1 = bias[c + 1];
                float v0 = fmaxf(acc[fm][fn][0] + b0, 0.f);
                float v1 = fmaxf(acc[fm][fn][1] + b1, 0.f);
                float v2 = fmaxf(acc[fm][fn][2] + b0, 0.f);
                float v3 = fmaxf(acc[fm][fn][3] + b1, 0.f);
                if (r < M)
                    *(__nv_bfloat162*)(C16 + (size_t)r * BN + c) =
                        __float22bfloat162_rn(make_float2(v0, v1));
                if (r + 8 < M)
                    *(__nv_bfloat162*)(C16 + (size_t)(r + 8) * BN + c) =
                        __float22bfloat162_rn(make_float2(v2, v3));
            }
        }
    }
}

// ---------------- dist layer0 : y = relu(e[M,5] @ W0[5,128] + b0) -> bf16 ----------------
#define D0_ROWS 16
__global__ void dist0_kernel(const float* __restrict__ e, const float* __restrict__ W0,
                             const float* __restrict__ b0,
                             __nv_bfloat16* __restrict__ y, int M)
{
    __shared__ float ws[KD * HD];
    for (int i = threadIdx.x; i < KD * HD; i += blockDim.x) ws[i] = W0[i];
    __syncthreads();
    int c = threadIdx.x;
    float bv = b0[c];
    int r0 = blockIdx.x * D0_ROWS;
    for (int rr = 0; rr < D0_ROWS; ++rr) {
        int r = r0 + rr;
        if (r >= M) return;
        float acc = bv;
#pragma unroll
        for (int k = 0; k < KD; ++k)
            acc += e[(size_t)r * KD + k] * ws[k * HD + c];
        y[(size_t)r * HD + c] = __float2bfloat16(fmaxf(acc, 0.f));
    }
}

// ---------------- sigmoid epilogue ----------------
__global__ void sigmoid_kernel(float* __restrict__ out, int M) {
    int i = blockIdx.x * blockDim.x + threadIdx.x;
    if (i >= M) return;
    float v = out[i] + g_cc;
    out[i] = 1.0f / (1.0f + __expf(-v));
}

// ---------------- launch ----------------
extern "C" void kernel_launch(void* const* d_in, const int* in_sizes, int n_in,
                              void* d_out, int out_size)
{
    const float* x          = (const float*)d_in[0];
    const void*  edge_index = d_in[1];
    const float* edge_attr  = (const float*)d_in[2];
    const float* pre_W      = (const float*)d_in[3];
    const float* pre_b      = (const float*)d_in[4];
    const float* c1_Ws      = (const float*)d_in[5];
    const float* c1_Wn      = (const float*)d_in[6];
    const float* c1_b       = (const float*)d_in[7];
    const float* c2_Ws      = (const float*)d_in[8];
    const float* c2_Wn      = (const float*)d_in[9];
    const float* c2_b       = (const float*)d_in[10];
    const float* np_W       = (const float*)d_in[11];
    const float* np_b       = (const float*)d_in[12];
    const float* d_W0       = (const float*)d_in[13];
    const float* d_b0       = (const float*)d_in[14];
    const float* d_W1       = (const float*)d_in[15];
    const float* d_b1       = (const float*)d_in[16];
    const float* d_W2       = (const float*)d_in[17];
    const float* d_b2       = (const float*)d_in[18];
    const float* d_W3       = (const float*)d_in[19];
    const float* d_b3       = (const float*)d_in[20];
    const float* final_W    = (const float*)d_in[21];
    const float* final_b    = (const float*)d_in[22];
    float* out = (float*)d_out;

    int M = NN;
    int E = in_sizes[1] / 2;
    if (E > EE) E = EE;

    __nv_bfloat16 *hb16, *h2b16, *aggb16, *y0b16, *y1b16, *wt;
    cudaGetSymbolAddress((void**)&hb16,   g_hb16);
    cudaGetSymbolAddress((void**)&h2b16,  g_h2b16);
    cudaGetSymbolAddress((void**)&aggb16, g_aggb16);
    cudaGetSymbolAddress((void**)&y0b16,  g_y0b16);
    cudaGetSymbolAddress((void**)&y1b16,  g_y1b16);
    cudaGetSymbolAddress((void**)&wt,     g_wt);

    cudaFuncSetAttribute(pre_gemm_kernel,
                         cudaFuncAttributeMaxDynamicSharedMemorySize, PRE_SMEM);

    // --- CSR build (direct from edge_index, 32-bit reads) ---
    zero_detect_kernel<<<(M + 255) / 256, 256>>>(out, M, (const unsigned*)edge_index);
    histogram_kernel<<<(E + 255) / 256, 256>>>((const int*)edge_index, E);
    int nb = (M + 1023) / 1024;
    scan1_kernel<<<nb, 1024>>>(M);
    scan2_kernel<<<1, 128>>>(nb);
    scan3_kernel<<<(M + 255) / 256, 256>>>(M, E);
    scatter_csr_kernel<<<(E + 255) / 256, 256>>>((const int*)edge_index, E);

    // --- constant prep (fold + weight transposes, one launch) ---
    int prep_elems = 6 * HD * HD + HD * FIN;
    prep_kernel<<<1 + (prep_elems + 255) / 256, 256>>>(
        np_W, np_b, d_W3, d_b3, final_W, final_b,
        c1_Ws, c1_Wn, c2_Ws, c2_Wn, d_W1, d_W2, pre_W);

    const __nv_bfloat16* wt_c1s = wt + 0 * HD * HD;
    const __nv_bfloat16* wt_c1n = wt + 1 * HD * HD;
    const __nv_bfloat16* wt_c2s = wt + 2 * HD * HD;
    const __nv_bfloat16* wt_c2n = wt + 3 * HD * HD;
    const __nv_bfloat16* wt_d1  = wt + 4 * HD * HD;
    const __nv_bfloat16* wt_d2  = wt + 5 * HD * HD;
    const __nv_bfloat16* wt_pre = wt + 6 * HD * HD;

    int G = (M + BM - 1) / BM;

    // --- pre layer (bf16 MMA, fp32 A converted at fragment load) + dist0 ---
    pre_gemm_kernel<<<G, 256, PRE_SMEM>>>(x, wt_pre, pre_b, hb16, M);
    dist0_kernel<<<(M + D0_ROWS - 1) / D0_ROWS, 128>>>(edge_attr, d_W0, d_b0, y0b16, M);

    // --- agg1 ---
    mean_agg_kernel<<<(M * 16 + 255) / 256, 256>>>(hb16, aggb16, M);

    // --- layer1 conv (c1) + dist layer1 (d1), batched, relu'd bf16 outs ---
    bf16_gemm_dual<<<2 * G, 256>>>(
        hb16, wt_c1s, aggb16, wt_c1n, c1_b, h2b16, 0,
        y0b16, wt_d1, d_b1, y1b16, 0,
        nullptr, M, G);

    // --- agg2 ---
    mean_agg_kernel<<<(M * 16 + 255) / 256, 256>>>(h2b16, aggb16, M);

    // --- layer2 conv (c2) + dist layer2 (d2), batched, fused final dot ---
    bf16_gemm_dual<<<2 * G, 256>>>(
        h2b16, wt_c2s, aggb16, wt_c2n, c2_b, nullptr, 1,
        y1b16, wt_d2, d_b2, nullptr, 2,
        out, M, G);

    // --- sigmoid ---
    sigmoid_kernel<<<(M + 255) / 256, 256>>>(out, M);
}